// round 6
// baseline (speedup 1.0000x reference)
#include <cuda_runtime.h>
#include <cuda_bf16.h>
#include <math.h>

#define BB   4
#define SS   2048
#define EMB  512
#define NH   8
#define DK   64
#define BSROWS (BB*SS)   // 8192
#define BH   (BB*NH)     // 32
#define NCT  (SS/64)     // 32 col tiles in scores

__device__ __nv_bfloat16 g_qh[BH * SS * DK];
__device__ __nv_bfloat16 g_ql[BH * SS * DK];
__device__ __nv_bfloat16 g_kh[BH * SS * DK];
__device__ __nv_bfloat16 g_kl[BH * SS * DK];
__device__ __nv_bfloat16 g_vh[BH * SS * DK];
__device__ __nv_bfloat16 g_vl[BH * SS * DK];
__device__ float g_ctx[BSROWS * EMB];
__device__ float g_x[BSROWS * EMB];
// softmax stats: per (row, col-tile) partial max / exp-sum, then per-row m & 1/sum
__device__ float g_smax[(size_t)BH * SS * NCT];
__device__ float g_ssum[(size_t)BH * SS * NCT];
__device__ float g_rowm[(size_t)BH * SS];
__device__ float g_rinv[(size_t)BH * SS];

// ---------------------------------------------------------------------------
// helpers
// ---------------------------------------------------------------------------
__device__ __forceinline__ unsigned sptr(const void* p) {
    return (unsigned)__cvta_generic_to_shared(p);
}
__device__ __forceinline__ void ldsm4(unsigned* r, unsigned a) {
    asm volatile("ldmatrix.sync.aligned.m8n8.x4.shared.b16 {%0,%1,%2,%3}, [%4];"
                 : "=r"(r[0]), "=r"(r[1]), "=r"(r[2]), "=r"(r[3]) : "r"(a));
}
__device__ __forceinline__ void ldsm4t(unsigned* r, unsigned a) {
    asm volatile("ldmatrix.sync.aligned.m8n8.x4.trans.shared.b16 {%0,%1,%2,%3}, [%4];"
                 : "=r"(r[0]), "=r"(r[1]), "=r"(r[2]), "=r"(r[3]) : "r"(a));
}
__device__ __forceinline__ void mma_bf16(float* c, const unsigned* a, const unsigned* b) {
    asm volatile(
        "mma.sync.aligned.m16n8k16.row.col.f32.bf16.bf16.f32 "
        "{%0,%1,%2,%3},{%4,%5,%6,%7},{%8,%9},{%0,%1,%2,%3};"
        : "+f"(c[0]), "+f"(c[1]), "+f"(c[2]), "+f"(c[3])
        : "r"(a[0]), "r"(a[1]), "r"(a[2]), "r"(a[3]), "r"(b[0]), "r"(b[1]));
}
__device__ __forceinline__ void split_pair(float x, float y,
                                           __nv_bfloat162& h2, __nv_bfloat162& l2) {
    __nv_bfloat16 hx = __float2bfloat16_rn(x);
    __nv_bfloat16 hy = __float2bfloat16_rn(y);
    __nv_bfloat16 lx = __float2bfloat16_rn(x - __bfloat162float(hx));
    __nv_bfloat16 ly = __float2bfloat16_rn(y - __bfloat162float(hy));
    h2 = __halves2bfloat162(hx, hy);
    l2 = __halves2bfloat162(lx, ly);
}
__device__ __forceinline__ void cp16(unsigned dst, const void* src) {
    asm volatile("cp.async.cg.shared.global [%0], [%1], 16;" :: "r"(dst), "l"(src));
}
__device__ __forceinline__ void cp_commit_wait() {
    asm volatile("cp.async.commit_group;");
    asm volatile("cp.async.wait_group 0;");
}

// ---------------------------------------------------------------------------
// Scores: per (b,h) 128x64 tile of q @ k^T * 0.125, masked, fp32 to attn.
// Also emits per-(row, tile) max and exp-sum for fused softmax.
// 256 thr, 8 warps (4m x 2n), warp 32x32, 3 CTAs/SM.
// ---------------------------------------------------------------------------
#define SC_QH 0
#define SC_QL 18432
#define SC_KH 36864
#define SC_KL 46080
#define SC_SMEM 55296

__global__ __launch_bounds__(256, 3) void mma_scores(
    const unsigned char* __restrict__ mask, float* __restrict__ attn)
{
    extern __shared__ __align__(16) char smem_raw[];
    __nv_bfloat16 (*Qh)[72] = (__nv_bfloat16(*)[72])(smem_raw + SC_QH);
    __nv_bfloat16 (*Ql)[72] = (__nv_bfloat16(*)[72])(smem_raw + SC_QL);
    __nv_bfloat16 (*Kh)[72] = (__nv_bfloat16(*)[72])(smem_raw + SC_KH);
    __nv_bfloat16 (*Kl)[72] = (__nv_bfloat16(*)[72])(smem_raw + SC_KL);

    const int t = threadIdx.x, lane = t & 31, w = t >> 5;
    const int wm = w & 3, wn = w >> 2;
    const int bh = blockIdx.z, b = bh >> 3;
    const int r0 = blockIdx.y * 128, c0 = blockIdx.x * 64;
    const size_t base = (size_t)bh * SS * DK;

    #pragma unroll
    for (int i = 0; i < 12; i++) {
        int ch = t + i * 256;
        if (ch < 1024) {
            int r = ch >> 3, c8 = (ch & 7) * 8;
            cp16(sptr(&Qh[r][c8]), g_qh + base + (size_t)(r0 + r) * 64 + c8);
        } else if (ch < 2048) {
            int idx = ch - 1024, r = idx >> 3, c8 = (idx & 7) * 8;
            cp16(sptr(&Ql[r][c8]), g_ql + base + (size_t)(r0 + r) * 64 + c8);
        } else if (ch < 2560) {
            int idx = ch - 2048, r = idx >> 3, c8 = (idx & 7) * 8;
            cp16(sptr(&Kh[r][c8]), g_kh + base + (size_t)(c0 + r) * 64 + c8);
        } else {
            int idx = ch - 2560, r = idx >> 3, c8 = (idx & 7) * 8;
            cp16(sptr(&Kl[r][c8]), g_kl + base + (size_t)(c0 + r) * 64 + c8);
        }
    }
    cp_commit_wait();
    __syncthreads();

    float acc[2][4][4] = {};
    #pragma unroll
    for (int k2 = 0; k2 < 64; k2 += 16) {
        unsigned ah[2][4], al[2][4];
        #pragma unroll
        for (int mi = 0; mi < 2; mi++) {
            int r = wm * 32 + mi * 16 + (lane & 15);
            int c = k2 + ((lane >> 4) << 3);
            ldsm4(ah[mi], sptr(&Qh[r][c]));
            ldsm4(al[mi], sptr(&Ql[r][c]));
        }
        #pragma unroll
        for (int g = 0; g < 2; g++) {
            int nr = wn * 32 + g * 16 + (lane & 7) + ((lane >> 4) << 3);
            int kc = k2 + (((lane >> 3) & 1) << 3);
            unsigned bh_[4], bl_[4];
            ldsm4(bh_, sptr(&Kh[nr][kc]));
            ldsm4(bl_, sptr(&Kl[nr][kc]));
            #pragma unroll
            for (int mi = 0; mi < 2; mi++) {
                mma_bf16(acc[mi][2*g],   ah[mi], &bh_[0]);
                mma_bf16(acc[mi][2*g+1], ah[mi], &bh_[2]);
                mma_bf16(acc[mi][2*g],   ah[mi], &bl_[0]);
                mma_bf16(acc[mi][2*g+1], ah[mi], &bl_[2]);
                mma_bf16(acc[mi][2*g],   al[mi], &bh_[0]);
                mma_bf16(acc[mi][2*g+1], al[mi], &bh_[2]);
            }
        }
    }

    // epilogue: mask+scale into acc, write to gmem
    #pragma unroll
    for (int mi = 0; mi < 2; mi++) {
        #pragma unroll
        for (int nf = 0; nf < 4; nf++) {
            float* c = acc[mi][nf];
            int m = r0 + wm * 32 + mi * 16 + (lane >> 2);
            int n = c0 + wn * 32 + nf * 8 + ((lane & 3) << 1);
            const unsigned char* mp = mask + ((size_t)b * SS + m) * SS + n;
            c[0] = mp[0] ? -1e9f : c[0] * 0.125f;
            c[1] = mp[1] ? -1e9f : c[1] * 0.125f;
            *(float2*)(attn + ((size_t)bh * SS + m) * SS + n) = make_float2(c[0], c[1]);
            mp = mask + ((size_t)b * SS + m + 8) * SS + n;
            c[2] = mp[0] ? -1e9f : c[2] * 0.125f;
            c[3] = mp[1] ? -1e9f : c[3] * 0.125f;
            *(float2*)(attn + ((size_t)bh * SS + m + 8) * SS + n) = make_float2(c[2], c[3]);
        }
    }

    // ---- per-row tile stats (max, exp-sum) -------------------------------
    __syncthreads();                       // done with Q/K smem, reuse it
    float* red  = (float*)smem_raw;        // [2][128] maxes
    float* red2 = red + 256;               // [2][128] sums

    float tmax[4];
    #pragma unroll
    for (int s2 = 0; s2 < 4; s2++) {       // slots: (mi, half)
        int mi = s2 >> 1, hf = (s2 & 1) * 2;
        float mx = fmaxf(fmaxf(acc[mi][0][hf], acc[mi][0][hf+1]),
                         fmaxf(acc[mi][1][hf], acc[mi][1][hf+1]));
        mx = fmaxf(mx, fmaxf(acc[mi][2][hf], acc[mi][2][hf+1]));
        mx = fmaxf(mx, fmaxf(acc[mi][3][hf], acc[mi][3][hf+1]));
        mx = fmaxf(mx, __shfl_xor_sync(0xffffffffu, mx, 1));
        mx = fmaxf(mx, __shfl_xor_sync(0xffffffffu, mx, 2));
        tmax[s2] = mx;
    }
    if ((lane & 3) == 0) {
        #pragma unroll
        for (int s2 = 0; s2 < 4; s2++) {
            int row = wm * 32 + (s2 >> 1) * 16 + (s2 & 1) * 8 + (lane >> 2);
            red[wn * 128 + row] = tmax[s2];
        }
    }
    __syncthreads();
    #pragma unroll
    for (int s2 = 0; s2 < 4; s2++) {
        int row = wm * 32 + (s2 >> 1) * 16 + (s2 & 1) * 8 + (lane >> 2);
        tmax[s2] = fmaxf(red[row], red[128 + row]);
    }
    float tsum[4];
    #pragma unroll
    for (int s2 = 0; s2 < 4; s2++) {
        int mi = s2 >> 1, hf = (s2 & 1) * 2;
        float s = 0.f;
        #pragma unroll
        for (int nf = 0; nf < 4; nf++)
            s += __expf(acc[mi][nf][hf] - tmax[s2]) + __expf(acc[mi][nf][hf+1] - tmax[s2]);
        s += __shfl_xor_sync(0xffffffffu, s, 1);
        s += __shfl_xor_sync(0xffffffffu, s, 2);
        tsum[s2] = s;
    }
    if ((lane & 3) == 0) {
        #pragma unroll
        for (int s2 = 0; s2 < 4; s2++) {
            int row = wm * 32 + (s2 >> 1) * 16 + (s2 & 1) * 8 + (lane >> 2);
            red2[wn * 128 + row] = tsum[s2];
        }
    }
    __syncthreads();
    if (wn == 0 && (lane & 3) == 0) {
        #pragma unroll
        for (int s2 = 0; s2 < 4; s2++) {
            int row = wm * 32 + (s2 >> 1) * 16 + (s2 & 1) * 8 + (lane >> 2);
            size_t idx = ((size_t)bh * SS + r0 + row) * NCT + blockIdx.x;
            g_smax[idx] = tmax[s2];
            g_ssum[idx] = red2[row] + red2[128 + row];
        }
    }
}

// ---------------------------------------------------------------------------
// Combine tile stats into per-row max and 1/sum. One warp per row.
// ---------------------------------------------------------------------------
__global__ __launch_bounds__(256) void softmax_stats(
    float* __restrict__ rowm, float* __restrict__ rinv)
{
    const int w = threadIdx.x >> 5, lane = threadIdx.x & 31;
    const size_t rg = (size_t)blockIdx.x * 8 + w;    // 0 .. BH*SS-1
    float m_l = g_smax[rg * NCT + lane];
    float s_l = g_ssum[rg * NCT + lane];
    float m = m_l;
    #pragma unroll
    for (int o = 16; o; o >>= 1) m = fmaxf(m, __shfl_xor_sync(0xffffffffu, m, o));
    float c = __expf(m_l - m) * s_l;
    #pragma unroll
    for (int o = 16; o; o >>= 1) c += __shfl_xor_sync(0xffffffffu, c, o);
    if (lane == 0) { rowm[rg] = m; rinv[rg] = 1.0f / c; }
}

// ---------------------------------------------------------------------------
// Projection / out-proj GEMM (unchanged)
// ---------------------------------------------------------------------------
template<int OUTPROJ>
__global__ __launch_bounds__(256, 3) void mma_gemm512(
    const float* __restrict__ A, const float* __restrict__ W,
    const float* __restrict__ bias, const float* __restrict__ resid,
    __nv_bfloat16* __restrict__ Oh, __nv_bfloat16* __restrict__ Ol,
    float* __restrict__ Of)
{
    __shared__ __align__(16) __nv_bfloat16 Ah_s[128][40], Al_s[128][40];
    __shared__ __align__(16) __nv_bfloat16 Bh_s[32][72],  Bl_s[32][72];
    const int t = threadIdx.x, lane = t & 31, w = t >> 5;
    const int wm = w & 3, wn = w >> 2;
    const int row0 = blockIdx.y * 128, col0 = blockIdx.x * 64;

    float acc[2][4][4] = {};

    for (int kk = 0; kk < 512; kk += 32) {
        {
            int ar = t >> 1, ac = (t & 1) * 16;
            const float* p = A + (size_t)(row0 + ar) * 512 + kk + ac;
            #pragma unroll
            for (int i = 0; i < 16; i += 4) {
                float4 v = *(const float4*)(p + i);
                __nv_bfloat162 h2, l2;
                split_pair(v.x, v.y, h2, l2);
                *(__nv_bfloat162*)&Ah_s[ar][ac + i]     = h2;
                *(__nv_bfloat162*)&Al_s[ar][ac + i]     = l2;
                split_pair(v.z, v.w, h2, l2);
                *(__nv_bfloat162*)&Ah_s[ar][ac + i + 2] = h2;
                *(__nv_bfloat162*)&Al_s[ar][ac + i + 2] = l2;
            }
        }
        {
            int br = t >> 3, bc = (t & 7) * 8;
            const float* p = W + (size_t)(kk + br) * 512 + col0 + bc;
            #pragma unroll
            for (int i = 0; i < 8; i += 4) {
                float4 v = *(const float4*)(p + i);
                __nv_bfloat162 h2, l2;
                split_pair(v.x, v.y, h2, l2);
                *(__nv_bfloat162*)&Bh_s[br][bc + i]     = h2;
                *(__nv_bfloat162*)&Bl_s[br][bc + i]     = l2;
                split_pair(v.z, v.w, h2, l2);
                *(__nv_bfloat162*)&Bh_s[br][bc + i + 2] = h2;
                *(__nv_bfloat162*)&Bl_s[br][bc + i + 2] = l2;
            }
        }
        __syncthreads();
        #pragma unroll
        for (int k2 = 0; k2 < 32; k2 += 16) {
            unsigned ah[2][4], al[2][4];
            #pragma unroll
            for (int mi = 0; mi < 2; mi++) {
                int r = wm * 32 + mi * 16 + (lane & 15);
                int c = k2 + ((lane >> 4) << 3);
                ldsm4(ah[mi], sptr(&Ah_s[r][c]));
                ldsm4(al[mi], sptr(&Al_s[r][c]));
            }
            #pragma unroll
            for (int g = 0; g < 2; g++) {
                int kr = k2 + (lane & 7) + (((lane >> 3) & 1) << 3);
                int nc = wn * 32 + g * 16 + ((lane >> 4) << 3);
                unsigned bh_[4], bl_[4];
                ldsm4t(bh_, sptr(&Bh_s[kr][nc]));
                ldsm4t(bl_, sptr(&Bl_s[kr][nc]));
                #pragma unroll
                for (int mi = 0; mi < 2; mi++) {
                    mma_bf16(acc[mi][2*g],   ah[mi], &bh_[0]);
                    mma_bf16(acc[mi][2*g+1], ah[mi], &bh_[2]);
                    mma_bf16(acc[mi][2*g],   ah[mi], &bl_[0]);
                    mma_bf16(acc[mi][2*g+1], ah[mi], &bl_[2]);
                    mma_bf16(acc[mi][2*g],   al[mi], &bh_[0]);
                    mma_bf16(acc[mi][2*g+1], al[mi], &bh_[2]);
                }
            }
        }
        __syncthreads();
    }

    #pragma unroll
    for (int mi = 0; mi < 2; mi++) {
        #pragma unroll
        for (int nf = 0; nf < 4; nf++) {
            float* c = acc[mi][nf];
            int m = row0 + wm * 32 + mi * 16 + (lane >> 2);
            int n = col0 + wn * 32 + nf * 8 + ((lane & 3) << 1);
            float b0 = bias[n], b1 = bias[n + 1];
            if (OUTPROJ) {
                float2 r = *(const float2*)(resid + (size_t)m * 512 + n);
                *(float2*)(Of + (size_t)m * 512 + n) =
                    make_float2(c[0] + b0 + r.x, c[1] + b1 + r.y);
                r = *(const float2*)(resid + (size_t)(m + 8) * 512 + n);
                *(float2*)(Of + (size_t)(m + 8) * 512 + n) =
                    make_float2(c[2] + b0 + r.x, c[3] + b1 + r.y);
            } else {
                int h = n >> 6, d = n & 63;
                int b = m >> 11, s = m & 2047;
                __nv_bfloat162 h2, l2;
                size_t base = ((size_t)(b * NH + h) * SS + s) * DK + d;
                split_pair(c[0] + b0, c[1] + b1, h2, l2);
                *(__nv_bfloat162*)&Oh[base] = h2;
                *(__nv_bfloat162*)&Ol[base] = l2;
                base += 8 * (size_t)DK;
                split_pair(c[2] + b0, c[3] + b1, h2, l2);
                *(__nv_bfloat162*)&Oh[base] = h2;
                *(__nv_bfloat162*)&Ol[base] = l2;
            }
        }
    }
}

// ---------------------------------------------------------------------------
// Context + softmax normalize: reads raw scores, writes probs in-place,
// accumulates ctx = P @ V. 256 thr, 8 warps (4m x 2n), warp 32x32, K chunk 64.
// ---------------------------------------------------------------------------
__global__ __launch_bounds__(256, 3) void mma_context(
    float* __restrict__ attn, const float* __restrict__ rowm,
    const float* __restrict__ rinv, float* __restrict__ ctx)
{
    __shared__ __align__(16) __nv_bfloat16 Ph[128][72], Pl[128][72];
    __shared__ __align__(16) __nv_bfloat16 Vh[64][72],  Vl[64][72];
    const int t = threadIdx.x, lane = t & 31, w = t >> 5;
    const int wm = w & 3, wn = w >> 2;
    const int bh = blockIdx.y, r0 = blockIdx.x * 128;
    float* ap = attn + (size_t)bh * SS * SS;
    const size_t vbase = (size_t)bh * SS * DK;

    const int pr = t >> 1, pc = (t & 1) * 32;
    const float rm = rowm[(size_t)bh * SS + r0 + pr];
    const float ri = rinv[(size_t)bh * SS + r0 + pr];

    float acc[2][4][4] = {};

    for (int kk = 0; kk < SS; kk += 64) {
        #pragma unroll
        for (int i = 0; i < 4; i++) {
            int chunk = t + i * 256;
            int arr = chunk >> 9, idx = chunk & 511;
            int vr = idx >> 3, vc = (idx & 7) * 8;
            if (arr == 0)
                cp16(sptr(&Vh[vr][vc]), g_vh + vbase + (size_t)(kk + vr) * 64 + vc);
            else
                cp16(sptr(&Vl[vr][vc]), g_vl + vbase + (size_t)(kk + vr) * 64 + vc);
        }
        {
            float* p = ap + (size_t)(r0 + pr) * SS + kk + pc;
            #pragma unroll
            for (int i = 0; i < 32; i += 4) {
                float4 v = *(float4*)(p + i);
                v.x = __expf(v.x - rm) * ri;
                v.y = __expf(v.y - rm) * ri;
                v.z = __expf(v.z - rm) * ri;
                v.w = __expf(v.w - rm) * ri;
                *(float4*)(p + i) = v;               // final attn probabilities
                __nv_bfloat162 h2, l2;
                split_pair(v.x, v.y, h2, l2);
                *(__nv_bfloat162*)&Ph[pr][pc + i]     = h2;
                *(__nv_bfloat162*)&Pl[pr][pc + i]     = l2;
                split_pair(v.z, v.w, h2, l2);
                *(__nv_bfloat162*)&Ph[pr][pc + i + 2] = h2;
                *(__nv_bfloat162*)&Pl[pr][pc + i + 2] = l2;
            }
        }
        cp_commit_wait();
        __syncthreads();
        #pragma unroll
        for (int k2 = 0; k2 < 64; k2 += 16) {
            unsigned ah[2][4], al[2][4];
            #pragma unroll
            for (int mi = 0; mi < 2; mi++) {
                int r = wm * 32 + mi * 16 + (lane & 15);
                int c = k2 + ((lane >> 4) << 3);
                ldsm4(ah[mi], sptr(&Ph[r][c]));
                ldsm4(al[mi], sptr(&Pl[r][c]));
            }
            #pragma unroll
            for (int g = 0; g < 2; g++) {
                int kr = k2 + (lane & 7) + (((lane >> 3) & 1) << 3);
                int nc = wn * 32 + g * 16 + ((lane >> 4) << 3);
                unsigned bh_[4], bl_[4];
                ldsm4t(bh_, sptr(&Vh[kr][nc]));
                ldsm4t(bl_, sptr(&Vl[kr][nc]));
                #pragma unroll
                for (int mi = 0; mi < 2; mi++) {
                    mma_bf16(acc[mi][2*g],   ah[mi], &bh_[0]);
                    mma_bf16(acc[mi][2*g+1], ah[mi], &bh_[2]);
                    mma_bf16(acc[mi][2*g],   ah[mi], &bl_[0]);
                    mma_bf16(acc[mi][2*g+1], ah[mi], &bl_[2]);
                    mma_bf16(acc[mi][2*g],   al[mi], &bh_[0]);
                    mma_bf16(acc[mi][2*g+1], al[mi], &bh_[2]);
                }
            }
        }
        __syncthreads();
    }

    const int b = bh >> 3, h = bh & 7;
    #pragma unroll
    for (int mi = 0; mi < 2; mi++) {
        #pragma unroll
        for (int nf = 0; nf < 4; nf++) {
            float* c = acc[mi][nf];
            int m = r0 + wm * 32 + mi * 16 + (lane >> 2);
            int n = wn * 32 + nf * 8 + ((lane & 3) << 1);
            *(float2*)(ctx + ((size_t)(b * SS + m)) * EMB + h * DK + n) =
                make_float2(c[0], c[1]);
            *(float2*)(ctx + ((size_t)(b * SS + m + 8)) * EMB + h * DK + n) =
                make_float2(c[2], c[3]);
        }
    }
}

// ---------------------------------------------------------------------------
// LayerNorm over 512.
// ---------------------------------------------------------------------------
__global__ __launch_bounds__(128) void ln_kernel(
    const float* __restrict__ gamma, const float* __restrict__ beta,
    float* __restrict__ out)
{
    const size_t row = blockIdx.x;
    const int t = threadIdx.x;
    const float* x = g_x + row * EMB;
    __shared__ float rs[4], rq[4];

    float4 v = ((const float4*)x)[t];
    float s  = v.x + v.y + v.z + v.w;
    float sq = v.x*v.x + v.y*v.y + v.z*v.z + v.w*v.w;
    #pragma unroll
    for (int o = 16; o; o >>= 1) {
        s  += __shfl_xor_sync(0xffffffffu, s,  o);
        sq += __shfl_xor_sync(0xffffffffu, sq, o);
    }
    if ((t & 31) == 0) { rs[t >> 5] = s; rq[t >> 5] = sq; }
    __syncthreads();
    s  = rs[0] + rs[1] + rs[2] + rs[3];
    sq = rq[0] + rq[1] + rq[2] + rq[3];

    float mu  = s * (1.0f / 512.0f);
    float var = sq * (1.0f / 512.0f) - mu * mu;
    float inv = rsqrtf(var + 1e-5f);

    float4 g = ((const float4*)gamma)[t];
    float4 bb = ((const float4*)beta)[t];
    float4 o;
    o.x = (v.x - mu) * inv * g.x + bb.x;
    o.y = (v.y - mu) * inv * g.y + bb.y;
    o.z = (v.z - mu) * inv * g.z + bb.z;
    o.w = (v.w - mu) * inv * g.w + bb.w;
    ((float4*)(out + row * EMB))[t] = o;
}

// ---------------------------------------------------------------------------
extern "C" void kernel_launch(void* const* d_in, const int* in_sizes, int n_in,
                              void* d_out, int out_size)
{
    const float* Q  = (const float*)d_in[0];
    const float* K  = (const float*)d_in[1];
    const float* V  = (const float*)d_in[2];
    const unsigned char* mask = (const unsigned char*)d_in[3];
    const float* Wq = (const float*)d_in[4];
    const float* bq = (const float*)d_in[5];
    const float* Wk = (const float*)d_in[6];
    const float* bk = (const float*)d_in[7];
    const float* Wv = (const float*)d_in[8];
    const float* bv = (const float*)d_in[9];
    const float* Wo = (const float*)d_in[10];
    const float* bo = (const float*)d_in[11];
    const float* gamma = (const float*)d_in[12];
    const float* beta  = (const float*)d_in[13];

    float* out  = (float*)d_out;
    float* attn = out + (size_t)BSROWS * EMB;

    __nv_bfloat16 *qh, *ql, *kh, *kl, *vh, *vl;
    float *ctxp, *xp, *rowmp, *rinvp;
    cudaGetSymbolAddress((void**)&qh, g_qh);
    cudaGetSymbolAddress((void**)&ql, g_ql);
    cudaGetSymbolAddress((void**)&kh, g_kh);
    cudaGetSymbolAddress((void**)&kl, g_kl);
    cudaGetSymbolAddress((void**)&vh, g_vh);
    cudaGetSymbolAddress((void**)&vl, g_vl);
    cudaGetSymbolAddress((void**)&ctxp, g_ctx);
    cudaGetSymbolAddress((void**)&xp,   g_x);
    cudaGetSymbolAddress((void**)&rowmp, g_rowm);
    cudaGetSymbolAddress((void**)&rinvp, g_rinv);

    cudaFuncSetAttribute(mma_scores, cudaFuncAttributeMaxDynamicSharedMemorySize,
                         SC_SMEM);

    dim3 gemm_grid(EMB / 64, BSROWS / 128);        // 8 x 64
    mma_gemm512<0><<<gemm_grid, 256>>>(Q, Wq, bq, nullptr, qh, ql, nullptr);
    mma_gemm512<0><<<gemm_grid, 256>>>(K, Wk, bk, nullptr, kh, kl, nullptr);
    mma_gemm512<0><<<gemm_grid, 256>>>(V, Wv, bv, nullptr, vh, vl, nullptr);

    dim3 sc_grid(SS / 64, SS / 128, BH);           // 32 x 16 x 32
    mma_scores<<<sc_grid, 256, SC_SMEM>>>(mask, attn);

    softmax_stats<<<(BH * SS) / 8, 256>>>(rowmp, rinvp);

    dim3 ctx_grid(SS / 128, BH);                   // 16 x 32
    mma_context<<<ctx_grid, 256>>>(attn, rowmp, rinvp, ctxp);

    mma_gemm512<1><<<gemm_grid, 256>>>(ctxp, Wo, bo, Q, nullptr, nullptr, xp);

    ln_kernel<<<BSROWS, 128>>>(gamma, beta, out);
}

// round 8
// speedup vs baseline: 2.6208x; 2.6208x over previous
#include <cuda_runtime.h>
#include <cuda_bf16.h>
#include <math.h>

#define BB   4
#define SS   2048
#define EMB  512
#define NH   8
#define DK   64
#define BSROWS (BB*SS)   // 8192
#define BH   (BB*NH)     // 32
#define NCT  (SS/64)     // 32 col tiles in scores

__device__ __nv_bfloat16 g_qh[BH * SS * DK];
__device__ __nv_bfloat16 g_ql[BH * SS * DK];
__device__ __nv_bfloat16 g_kh[BH * SS * DK];
__device__ __nv_bfloat16 g_kl[BH * SS * DK];
__device__ __nv_bfloat16 g_vh[BH * SS * DK];
__device__ __nv_bfloat16 g_vl[BH * SS * DK];
__device__ float g_ctx[BSROWS * EMB];
__device__ float g_x[BSROWS * EMB];
// softmax stats: per (row, col-tile) partial max / exp-sum, then per-row m & 1/sum
__device__ float g_smax[(size_t)BH * SS * NCT];
__device__ float g_ssum[(size_t)BH * SS * NCT];
__device__ float g_rowm[(size_t)BH * SS];
__device__ float g_rinv[(size_t)BH * SS];

// ---------------------------------------------------------------------------
// helpers
// ---------------------------------------------------------------------------
__device__ __forceinline__ unsigned sptr(const void* p) {
    return (unsigned)__cvta_generic_to_shared(p);
}
__device__ __forceinline__ void ldsm4(unsigned* r, unsigned a) {
    asm volatile("ldmatrix.sync.aligned.m8n8.x4.shared.b16 {%0,%1,%2,%3}, [%4];"
                 : "=r"(r[0]), "=r"(r[1]), "=r"(r[2]), "=r"(r[3]) : "r"(a));
}
__device__ __forceinline__ void ldsm4t(unsigned* r, unsigned a) {
    asm volatile("ldmatrix.sync.aligned.m8n8.x4.trans.shared.b16 {%0,%1,%2,%3}, [%4];"
                 : "=r"(r[0]), "=r"(r[1]), "=r"(r[2]), "=r"(r[3]) : "r"(a));
}
__device__ __forceinline__ void mma_bf16(float* c, const unsigned* a, const unsigned* b) {
    asm volatile(
        "mma.sync.aligned.m16n8k16.row.col.f32.bf16.bf16.f32 "
        "{%0,%1,%2,%3},{%4,%5,%6,%7},{%8,%9},{%0,%1,%2,%3};"
        : "+f"(c[0]), "+f"(c[1]), "+f"(c[2]), "+f"(c[3])
        : "r"(a[0]), "r"(a[1]), "r"(a[2]), "r"(a[3]), "r"(b[0]), "r"(b[1]));
}
__device__ __forceinline__ void split_pair(float x, float y,
                                           __nv_bfloat162& h2, __nv_bfloat162& l2) {
    __nv_bfloat16 hx = __float2bfloat16_rn(x);
    __nv_bfloat16 hy = __float2bfloat16_rn(y);
    __nv_bfloat16 lx = __float2bfloat16_rn(x - __bfloat162float(hx));
    __nv_bfloat16 ly = __float2bfloat16_rn(y - __bfloat162float(hy));
    h2 = __halves2bfloat162(hx, hy);
    l2 = __halves2bfloat162(lx, ly);
}
__device__ __forceinline__ void cp16(unsigned dst, const void* src) {
    asm volatile("cp.async.cg.shared.global [%0], [%1], 16;" :: "r"(dst), "l"(src));
}
__device__ __forceinline__ void cp_commit_wait() {
    asm volatile("cp.async.commit_group;");
    asm volatile("cp.async.wait_group 0;");
}

// ---------------------------------------------------------------------------
// Scores: per (b,h) 128x64 tile of q @ k^T * 0.125, masked, fp32 to attn.
// Also emits per-(row, tile) max and exp-sum for fused softmax.
// 256 thr, 8 warps (4m x 2n), warp 32x32, 3 CTAs/SM.
// ---------------------------------------------------------------------------
#define SC_QH 0
#define SC_QL 18432
#define SC_KH 36864
#define SC_KL 46080
#define SC_SMEM 55296

__global__ __launch_bounds__(256, 3) void mma_scores(
    const unsigned char* __restrict__ mask, float* __restrict__ attn)
{
    extern __shared__ __align__(16) char smem_raw[];
    __nv_bfloat16 (*Qh)[72] = (__nv_bfloat16(*)[72])(smem_raw + SC_QH);
    __nv_bfloat16 (*Ql)[72] = (__nv_bfloat16(*)[72])(smem_raw + SC_QL);
    __nv_bfloat16 (*Kh)[72] = (__nv_bfloat16(*)[72])(smem_raw + SC_KH);
    __nv_bfloat16 (*Kl)[72] = (__nv_bfloat16(*)[72])(smem_raw + SC_KL);

    const int t = threadIdx.x, lane = t & 31, w = t >> 5;
    const int wm = w & 3, wn = w >> 2;
    const int bh = blockIdx.z, b = bh >> 3;
    const int r0 = blockIdx.y * 128, c0 = blockIdx.x * 64;
    const size_t base = (size_t)bh * SS * DK;

    #pragma unroll
    for (int i = 0; i < 12; i++) {
        int ch = t + i * 256;
        if (ch < 1024) {
            int r = ch >> 3, c8 = (ch & 7) * 8;
            cp16(sptr(&Qh[r][c8]), g_qh + base + (size_t)(r0 + r) * 64 + c8);
        } else if (ch < 2048) {
            int idx = ch - 1024, r = idx >> 3, c8 = (idx & 7) * 8;
            cp16(sptr(&Ql[r][c8]), g_ql + base + (size_t)(r0 + r) * 64 + c8);
        } else if (ch < 2560) {
            int idx = ch - 2048, r = idx >> 3, c8 = (idx & 7) * 8;
            cp16(sptr(&Kh[r][c8]), g_kh + base + (size_t)(c0 + r) * 64 + c8);
        } else {
            int idx = ch - 2560, r = idx >> 3, c8 = (idx & 7) * 8;
            cp16(sptr(&Kl[r][c8]), g_kl + base + (size_t)(c0 + r) * 64 + c8);
        }
    }
    cp_commit_wait();
    __syncthreads();

    float acc[2][4][4] = {};
    #pragma unroll
    for (int k2 = 0; k2 < 64; k2 += 16) {
        unsigned ah[2][4], al[2][4];
        #pragma unroll
        for (int mi = 0; mi < 2; mi++) {
            int r = wm * 32 + mi * 16 + (lane & 15);
            int c = k2 + ((lane >> 4) << 3);
            ldsm4(ah[mi], sptr(&Qh[r][c]));
            ldsm4(al[mi], sptr(&Ql[r][c]));
        }
        #pragma unroll
        for (int g = 0; g < 2; g++) {
            int nr = wn * 32 + g * 16 + (lane & 7) + ((lane >> 4) << 3);
            int kc = k2 + (((lane >> 3) & 1) << 3);
            unsigned bh_[4], bl_[4];
            ldsm4(bh_, sptr(&Kh[nr][kc]));
            ldsm4(bl_, sptr(&Kl[nr][kc]));
            #pragma unroll
            for (int mi = 0; mi < 2; mi++) {
                mma_bf16(acc[mi][2*g],   ah[mi], &bh_[0]);
                mma_bf16(acc[mi][2*g+1], ah[mi], &bh_[2]);
                mma_bf16(acc[mi][2*g],   ah[mi], &bl_[0]);
                mma_bf16(acc[mi][2*g+1], ah[mi], &bl_[2]);
                mma_bf16(acc[mi][2*g],   al[mi], &bh_[0]);
                mma_bf16(acc[mi][2*g+1], al[mi], &bh_[2]);
            }
        }
    }

    // epilogue: mask+scale into acc, write to gmem
    #pragma unroll
    for (int mi = 0; mi < 2; mi++) {
        #pragma unroll
        for (int nf = 0; nf < 4; nf++) {
            float* c = acc[mi][nf];
            int m = r0 + wm * 32 + mi * 16 + (lane >> 2);
            int n = c0 + wn * 32 + nf * 8 + ((lane & 3) << 1);
            const unsigned char* mp = mask + ((size_t)b * SS + m) * SS + n;
            c[0] = mp[0] ? -1e9f : c[0] * 0.125f;
            c[1] = mp[1] ? -1e9f : c[1] * 0.125f;
            *(float2*)(attn + ((size_t)bh * SS + m) * SS + n) = make_float2(c[0], c[1]);
            mp = mask + ((size_t)b * SS + m + 8) * SS + n;
            c[2] = mp[0] ? -1e9f : c[2] * 0.125f;
            c[3] = mp[1] ? -1e9f : c[3] * 0.125f;
            *(float2*)(attn + ((size_t)bh * SS + m + 8) * SS + n) = make_float2(c[2], c[3]);
        }
    }

    // ---- per-row tile stats (max, exp-sum) -------------------------------
    __syncthreads();                       // done with Q/K smem, reuse it
    float* red  = (float*)smem_raw;        // [2][128] maxes
    float* red2 = red + 256;               // [2][128] sums

    float tmax[4];
    #pragma unroll
    for (int s2 = 0; s2 < 4; s2++) {       // slots: (mi, half)
        int mi = s2 >> 1, hf = (s2 & 1) * 2;
        float mx = fmaxf(fmaxf(acc[mi][0][hf], acc[mi][0][hf+1]),
                         fmaxf(acc[mi][1][hf], acc[mi][1][hf+1]));
        mx = fmaxf(mx, fmaxf(acc[mi][2][hf], acc[mi][2][hf+1]));
        mx = fmaxf(mx, fmaxf(acc[mi][3][hf], acc[mi][3][hf+1]));
        mx = fmaxf(mx, __shfl_xor_sync(0xffffffffu, mx, 1));
        mx = fmaxf(mx, __shfl_xor_sync(0xffffffffu, mx, 2));
        tmax[s2] = mx;
    }
    if ((lane & 3) == 0) {
        #pragma unroll
        for (int s2 = 0; s2 < 4; s2++) {
            int row = wm * 32 + (s2 >> 1) * 16 + (s2 & 1) * 8 + (lane >> 2);
            red[wn * 128 + row] = tmax[s2];
        }
    }
    __syncthreads();
    #pragma unroll
    for (int s2 = 0; s2 < 4; s2++) {
        int row = wm * 32 + (s2 >> 1) * 16 + (s2 & 1) * 8 + (lane >> 2);
        tmax[s2] = fmaxf(red[row], red[128 + row]);
    }
    float tsum[4];
    #pragma unroll
    for (int s2 = 0; s2 < 4; s2++) {
        int mi = s2 >> 1, hf = (s2 & 1) * 2;
        float s = 0.f;
        #pragma unroll
        for (int nf = 0; nf < 4; nf++)
            s += __expf(acc[mi][nf][hf] - tmax[s2]) + __expf(acc[mi][nf][hf+1] - tmax[s2]);
        s += __shfl_xor_sync(0xffffffffu, s, 1);
        s += __shfl_xor_sync(0xffffffffu, s, 2);
        tsum[s2] = s;
    }
    if ((lane & 3) == 0) {
        #pragma unroll
        for (int s2 = 0; s2 < 4; s2++) {
            int row = wm * 32 + (s2 >> 1) * 16 + (s2 & 1) * 8 + (lane >> 2);
            red2[wn * 128 + row] = tsum[s2];
        }
    }
    __syncthreads();
    if (wn == 0 && (lane & 3) == 0) {
        #pragma unroll
        for (int s2 = 0; s2 < 4; s2++) {
            int row = wm * 32 + (s2 >> 1) * 16 + (s2 & 1) * 8 + (lane >> 2);
            size_t idx = ((size_t)bh * SS + r0 + row) * NCT + blockIdx.x;
            g_smax[idx] = tmax[s2];
            g_ssum[idx] = red2[row] + red2[128 + row];
        }
    }
}

// ---------------------------------------------------------------------------
// Combine tile stats into per-row max and 1/sum. One warp per row.
// ---------------------------------------------------------------------------
__global__ __launch_bounds__(256) void softmax_stats(
    float* __restrict__ rowm, float* __restrict__ rinv)
{
    const int w = threadIdx.x >> 5, lane = threadIdx.x & 31;
    const size_t rg = (size_t)blockIdx.x * 8 + w;    // 0 .. BH*SS-1
    float m_l = g_smax[rg * NCT + lane];
    float s_l = g_ssum[rg * NCT + lane];
    float m = m_l;
    #pragma unroll
    for (int o = 16; o; o >>= 1) m = fmaxf(m, __shfl_xor_sync(0xffffffffu, m, o));
    float c = __expf(m_l - m) * s_l;
    #pragma unroll
    for (int o = 16; o; o >>= 1) c += __shfl_xor_sync(0xffffffffu, c, o);
    if (lane == 0) { rowm[rg] = m; rinv[rg] = 1.0f / c; }
}

// ---------------------------------------------------------------------------
// Projection / out-proj GEMM (unchanged)
// ---------------------------------------------------------------------------
template<int OUTPROJ>
__global__ __launch_bounds__(256, 3) void mma_gemm512(
    const float* __restrict__ A, const float* __restrict__ W,
    const float* __restrict__ bias, const float* __restrict__ resid,
    __nv_bfloat16* __restrict__ Oh, __nv_bfloat16* __restrict__ Ol,
    float* __restrict__ Of)
{
    __shared__ __align__(16) __nv_bfloat16 Ah_s[128][40], Al_s[128][40];
    __shared__ __align__(16) __nv_bfloat16 Bh_s[32][72],  Bl_s[32][72];
    const int t = threadIdx.x, lane = t & 31, w = t >> 5;
    const int wm = w & 3, wn = w >> 2;
    const int row0 = blockIdx.y * 128, col0 = blockIdx.x * 64;

    float acc[2][4][4] = {};

    for (int kk = 0; kk < 512; kk += 32) {
        {
            int ar = t >> 1, ac = (t & 1) * 16;
            const float* p = A + (size_t)(row0 + ar) * 512 + kk + ac;
            #pragma unroll
            for (int i = 0; i < 16; i += 4) {
                float4 v = *(const float4*)(p + i);
                __nv_bfloat162 h2, l2;
                split_pair(v.x, v.y, h2, l2);
                *(__nv_bfloat162*)&Ah_s[ar][ac + i]     = h2;
                *(__nv_bfloat162*)&Al_s[ar][ac + i]     = l2;
                split_pair(v.z, v.w, h2, l2);
                *(__nv_bfloat162*)&Ah_s[ar][ac + i + 2] = h2;
                *(__nv_bfloat162*)&Al_s[ar][ac + i + 2] = l2;
            }
        }
        {
            int br = t >> 3, bc = (t & 7) * 8;
            const float* p = W + (size_t)(kk + br) * 512 + col0 + bc;
            #pragma unroll
            for (int i = 0; i < 8; i += 4) {
                float4 v = *(const float4*)(p + i);
                __nv_bfloat162 h2, l2;
                split_pair(v.x, v.y, h2, l2);
                *(__nv_bfloat162*)&Bh_s[br][bc + i]     = h2;
                *(__nv_bfloat162*)&Bl_s[br][bc + i]     = l2;
                split_pair(v.z, v.w, h2, l2);
                *(__nv_bfloat162*)&Bh_s[br][bc + i + 2] = h2;
                *(__nv_bfloat162*)&Bl_s[br][bc + i + 2] = l2;
            }
        }
        __syncthreads();
        #pragma unroll
        for (int k2 = 0; k2 < 32; k2 += 16) {
            unsigned ah[2][4], al[2][4];
            #pragma unroll
            for (int mi = 0; mi < 2; mi++) {
                int r = wm * 32 + mi * 16 + (lane & 15);
                int c = k2 + ((lane >> 4) << 3);
                ldsm4(ah[mi], sptr(&Ah_s[r][c]));
                ldsm4(al[mi], sptr(&Al_s[r][c]));
            }
            #pragma unroll
            for (int g = 0; g < 2; g++) {
                int kr = k2 + (lane & 7) + (((lane >> 3) & 1) << 3);
                int nc = wn * 32 + g * 16 + ((lane >> 4) << 3);
                unsigned bh_[4], bl_[4];
                ldsm4t(bh_, sptr(&Bh_s[kr][nc]));
                ldsm4t(bl_, sptr(&Bl_s[kr][nc]));
                #pragma unroll
                for (int mi = 0; mi < 2; mi++) {
                    mma_bf16(acc[mi][2*g],   ah[mi], &bh_[0]);
                    mma_bf16(acc[mi][2*g+1], ah[mi], &bh_[2]);
                    mma_bf16(acc[mi][2*g],   ah[mi], &bl_[0]);
                    mma_bf16(acc[mi][2*g+1], ah[mi], &bl_[2]);
                    mma_bf16(acc[mi][2*g],   al[mi], &bh_[0]);
                    mma_bf16(acc[mi][2*g+1], al[mi], &bh_[2]);
                }
            }
        }
        __syncthreads();
    }

    #pragma unroll
    for (int mi = 0; mi < 2; mi++) {
        #pragma unroll
        for (int nf = 0; nf < 4; nf++) {
            float* c = acc[mi][nf];
            int m = row0 + wm * 32 + mi * 16 + (lane >> 2);
            int n = col0 + wn * 32 + nf * 8 + ((lane & 3) << 1);
            float b0 = bias[n], b1 = bias[n + 1];
            if (OUTPROJ) {
                float2 r = *(const float2*)(resid + (size_t)m * 512 + n);
                *(float2*)(Of + (size_t)m * 512 + n) =
                    make_float2(c[0] + b0 + r.x, c[1] + b1 + r.y);
                r = *(const float2*)(resid + (size_t)(m + 8) * 512 + n);
                *(float2*)(Of + (size_t)(m + 8) * 512 + n) =
                    make_float2(c[2] + b0 + r.x, c[3] + b1 + r.y);
            } else {
                int h = n >> 6, d = n & 63;
                int b = m >> 11, s = m & 2047;
                __nv_bfloat162 h2, l2;
                size_t base = ((size_t)(b * NH + h) * SS + s) * DK + d;
                split_pair(c[0] + b0, c[1] + b1, h2, l2);
                *(__nv_bfloat162*)&Oh[base] = h2;
                *(__nv_bfloat162*)&Ol[base] = l2;
                base += 8 * (size_t)DK;
                split_pair(c[2] + b0, c[3] + b1, h2, l2);
                *(__nv_bfloat162*)&Oh[base] = h2;
                *(__nv_bfloat162*)&Ol[base] = l2;
            }
        }
    }
}

// ---------------------------------------------------------------------------
// Context + softmax normalize: reads raw scores, writes probs in-place,
// accumulates ctx = P @ V.
// 256 thr, 8 warps (4m x 2n), warp 32x32, K chunk 64.
// NOTE: launch_bounds (256,2) — NOT 3. The (256,3) 80-reg clamp caused
// inner-loop spills once exp/rm/ri were added (round-6 6x regression).
// ---------------------------------------------------------------------------
__global__ __launch_bounds__(256, 2) void mma_context(
    float* __restrict__ attn, const float* __restrict__ rowm,
    const float* __restrict__ rinv, float* __restrict__ ctx)
{
    __shared__ __align__(16) __nv_bfloat16 Ph[128][72], Pl[128][72];
    __shared__ __align__(16) __nv_bfloat16 Vh[64][72],  Vl[64][72];
    const int t = threadIdx.x, lane = t & 31, w = t >> 5;
    const int wm = w & 3, wn = w >> 2;
    const int bh = blockIdx.y, r0 = blockIdx.x * 128;
    const size_t vbase = (size_t)bh * SS * DK;

    const int pr = t >> 1, pc = (t & 1) * 32;
    const float rm = __ldg(rowm + (size_t)bh * SS + r0 + pr);
    const float ri = __ldg(rinv + (size_t)bh * SS + r0 + pr);
    float* prow = attn + (size_t)bh * SS * SS + (size_t)(r0 + pr) * SS + pc;

    float acc[2][4][4] = {};

    for (int kk = 0; kk < SS; kk += 64) {
        #pragma unroll
        for (int i = 0; i < 4; i++) {
            int chunk = t + i * 256;
            int arr = chunk >> 9, idx = chunk & 511;
            int vr = idx >> 3, vc = (idx & 7) * 8;
            if (arr == 0)
                cp16(sptr(&Vh[vr][vc]), g_vh + vbase + (size_t)(kk + vr) * 64 + vc);
            else
                cp16(sptr(&Vl[vr][vc]), g_vl + vbase + (size_t)(kk + vr) * 64 + vc);
        }
        {
            float* p = prow + kk;
            #pragma unroll
            for (int i = 0; i < 32; i += 4) {
                float4 v = *(float4*)(p + i);
                v.x = __expf(v.x - rm) * ri;
                v.y = __expf(v.y - rm) * ri;
                v.z = __expf(v.z - rm) * ri;
                v.w = __expf(v.w - rm) * ri;
                *(float4*)(p + i) = v;               // final attn probabilities
                __nv_bfloat162 h2, l2;
                split_pair(v.x, v.y, h2, l2);
                *(__nv_bfloat162*)&Ph[pr][pc + i]     = h2;
                *(__nv_bfloat162*)&Pl[pr][pc + i]     = l2;
                split_pair(v.z, v.w, h2, l2);
                *(__nv_bfloat162*)&Ph[pr][pc + i + 2] = h2;
                *(__nv_bfloat162*)&Pl[pr][pc + i + 2] = l2;
            }
        }
        cp_commit_wait();
        __syncthreads();
        #pragma unroll
        for (int k2 = 0; k2 < 64; k2 += 16) {
            unsigned ah[2][4], al[2][4];
            #pragma unroll
            for (int mi = 0; mi < 2; mi++) {
                int r = wm * 32 + mi * 16 + (lane & 15);
                int c = k2 + ((lane >> 4) << 3);
                ldsm4(ah[mi], sptr(&Ph[r][c]));
                ldsm4(al[mi], sptr(&Pl[r][c]));
            }
            #pragma unroll
            for (int g = 0; g < 2; g++) {
                int kr = k2 + (lane & 7) + (((lane >> 3) & 1) << 3);
                int nc = wn * 32 + g * 16 + ((lane >> 4) << 3);
                unsigned bh_[4], bl_[4];
                ldsm4t(bh_, sptr(&Vh[kr][nc]));
                ldsm4t(bl_, sptr(&Vl[kr][nc]));
                #pragma unroll
                for (int mi = 0; mi < 2; mi++) {
                    mma_bf16(acc[mi][2*g],   ah[mi], &bh_[0]);
                    mma_bf16(acc[mi][2*g+1], ah[mi], &bh_[2]);
                    mma_bf16(acc[mi][2*g],   ah[mi], &bl_[0]);
                    mma_bf16(acc[mi][2*g+1], ah[mi], &bl_[2]);
                    mma_bf16(acc[mi][2*g],   al[mi], &bh_[0]);
                    mma_bf16(acc[mi][2*g+1], al[mi], &bh_[2]);
                }
            }
        }
        __syncthreads();
    }

    const int b = bh >> 3, h = bh & 7;
    #pragma unroll
    for (int mi = 0; mi < 2; mi++) {
        #pragma unroll
        for (int nf = 0; nf < 4; nf++) {
            float* c = acc[mi][nf];
            int m = r0 + wm * 32 + mi * 16 + (lane >> 2);
            int n = wn * 32 + nf * 8 + ((lane & 3) << 1);
            *(float2*)(ctx + ((size_t)(b * SS + m)) * EMB + h * DK + n) =
                make_float2(c[0], c[1]);
            *(float2*)(ctx + ((size_t)(b * SS + m + 8)) * EMB + h * DK + n) =
                make_float2(c[2], c[3]);
        }
    }
}

// ---------------------------------------------------------------------------
// LayerNorm over 512.
// ---------------------------------------------------------------------------
__global__ __launch_bounds__(128) void ln_kernel(
    const float* __restrict__ gamma, const float* __restrict__ beta,
    float* __restrict__ out)
{
    const size_t row = blockIdx.x;
    const int t = threadIdx.x;
    const float* x = g_x + row * EMB;
    __shared__ float rs[4], rq[4];

    float4 v = ((const float4*)x)[t];
    float s  = v.x + v.y + v.z + v.w;
    float sq = v.x*v.x + v.y*v.y + v.z*v.z + v.w*v.w;
    #pragma unroll
    for (int o = 16; o; o >>= 1) {
        s  += __shfl_xor_sync(0xffffffffu, s,  o);
        sq += __shfl_xor_sync(0xffffffffu, sq, o);
    }
    if ((t & 31) == 0) { rs[t >> 5] = s; rq[t >> 5] = sq; }
    __syncthreads();
    s  = rs[0] + rs[1] + rs[2] + rs[3];
    sq = rq[0] + rq[1] + rq[2] + rq[3];

    float mu  = s * (1.0f / 512.0f);
    float var = sq * (1.0f / 512.0f) - mu * mu;
    float inv = rsqrtf(var + 1e-5f);

    float4 g = ((const float4*)gamma)[t];
    float4 bb = ((const float4*)beta)[t];
    float4 o;
    o.x = (v.x - mu) * inv * g.x + bb.x;
    o.y = (v.y - mu) * inv * g.y + bb.y;
    o.z = (v.z - mu) * inv * g.z + bb.z;
    o.w = (v.w - mu) * inv * g.w + bb.w;
    ((float4*)(out + row * EMB))[t] = o;
}

// ---------------------------------------------------------------------------
extern "C" void kernel_launch(void* const* d_in, const int* in_sizes, int n_in,
                              void* d_out, int out_size)
{
    const float* Q  = (const float*)d_in[0];
    const float* K  = (const float*)d_in[1];
    const float* V  = (const float*)d_in[2];
    const unsigned char* mask = (const unsigned char*)d_in[3];
    const float* Wq = (const float*)d_in[4];
    const float* bq = (const float*)d_in[5];
    const float* Wk = (const float*)d_in[6];
    const float* bk = (const float*)d_in[7];
    const float* Wv = (const float*)d_in[8];
    const float* bv = (const float*)d_in[9];
    const float* Wo = (const float*)d_in[10];
    const float* bo = (const float*)d_in[11];
    const float* gamma = (const float*)d_in[12];
    const float* beta  = (const float*)d_in[13];

    float* out  = (float*)d_out;
    float* attn = out + (size_t)BSROWS * EMB;

    __nv_bfloat16 *qh, *ql, *kh, *kl, *vh, *vl;
    float *ctxp, *xp, *rowmp, *rinvp;
    cudaGetSymbolAddress((void**)&qh, g_qh);
    cudaGetSymbolAddress((void**)&ql, g_ql);
    cudaGetSymbolAddress((void**)&kh, g_kh);
    cudaGetSymbolAddress((void**)&kl, g_kl);
    cudaGetSymbolAddress((void**)&vh, g_vh);
    cudaGetSymbolAddress((void**)&vl, g_vl);
    cudaGetSymbolAddress((void**)&ctxp, g_ctx);
    cudaGetSymbolAddress((void**)&xp,   g_x);
    cudaGetSymbolAddress((void**)&rowmp, g_rowm);
    cudaGetSymbolAddress((void**)&rinvp, g_rinv);

    cudaFuncSetAttribute(mma_scores, cudaFuncAttributeMaxDynamicSharedMemorySize,
                         SC_SMEM);

    dim3 gemm_grid(EMB / 64, BSROWS / 128);        // 8 x 64
    mma_gemm512<0><<<gemm_grid, 256>>>(Q, Wq, bq, nullptr, qh, ql, nullptr);
    mma_gemm512<0><<<gemm_grid, 256>>>(K, Wk, bk, nullptr, kh, kl, nullptr);
    mma_gemm512<0><<<gemm_grid, 256>>>(V, Wv, bv, nullptr, vh, vl, nullptr);

    dim3 sc_grid(SS / 64, SS / 128, BH);           // 32 x 16 x 32
    mma_scores<<<sc_grid, 256, SC_SMEM>>>(mask, attn);

    softmax_stats<<<(BH * SS) / 8, 256>>>(rowmp, rinvp);

    dim3 ctx_grid(SS / 128, BH);                   // 16 x 32
    mma_context<<<ctx_grid, 256>>>(attn, rowmp, rinvp, ctxp);

    mma_gemm512<1><<<gemm_grid, 256>>>(ctxp, Wo, bo, Q, nullptr, nullptr, xp);

    ln_kernel<<<BSROWS, 128>>>(gamma, beta, out);
}

// round 9
// speedup vs baseline: 2.8356x; 1.0820x over previous
#include <cuda_runtime.h>
#include <cuda_bf16.h>
#include <math.h>

#define BB   4
#define SS   2048
#define EMB  512
#define NH   8
#define DK   64
#define BSROWS (BB*SS)   // 8192
#define BH   (BB*NH)     // 32
#define NCT  (SS/64)     // 32 col tiles in scores

// projection outputs (hi/lo bf16, head-major)
__device__ __nv_bfloat16 g_qh[BH * SS * DK];
__device__ __nv_bfloat16 g_ql[BH * SS * DK];
__device__ __nv_bfloat16 g_kh[BH * SS * DK];
__device__ __nv_bfloat16 g_kl[BH * SS * DK];
__device__ __nv_bfloat16 g_vh[BH * SS * DK];
__device__ __nv_bfloat16 g_vl[BH * SS * DK];
// pre-split inputs
__device__ __nv_bfloat16 g_inqh[BSROWS * EMB], g_inql[BSROWS * EMB];
__device__ __nv_bfloat16 g_inkh[BSROWS * EMB], g_inkl[BSROWS * EMB];
__device__ __nv_bfloat16 g_invh[BSROWS * EMB], g_invl[BSROWS * EMB];
// pre-split weights
__device__ __nv_bfloat16 g_wqh[EMB * EMB], g_wql[EMB * EMB];
__device__ __nv_bfloat16 g_wkh[EMB * EMB], g_wkl[EMB * EMB];
__device__ __nv_bfloat16 g_wvh[EMB * EMB], g_wvl[EMB * EMB];
__device__ __nv_bfloat16 g_woh[EMB * EMB], g_wol[EMB * EMB];
// context (hi/lo bf16) + pre-LN sum
__device__ __nv_bfloat16 g_ctxh[BSROWS * EMB], g_ctxl[BSROWS * EMB];
__device__ float g_x[BSROWS * EMB];
// softmax stats
__device__ float g_smax[(size_t)BH * SS * NCT];
__device__ float g_ssum[(size_t)BH * SS * NCT];
__device__ float g_rowm[(size_t)BH * SS];
__device__ float g_rinv[(size_t)BH * SS];

// ---------------------------------------------------------------------------
// helpers
// ---------------------------------------------------------------------------
__device__ __forceinline__ unsigned sptr(const void* p) {
    return (unsigned)__cvta_generic_to_shared(p);
}
__device__ __forceinline__ void ldsm4(unsigned* r, unsigned a) {
    asm volatile("ldmatrix.sync.aligned.m8n8.x4.shared.b16 {%0,%1,%2,%3}, [%4];"
                 : "=r"(r[0]), "=r"(r[1]), "=r"(r[2]), "=r"(r[3]) : "r"(a));
}
__device__ __forceinline__ void ldsm4t(unsigned* r, unsigned a) {
    asm volatile("ldmatrix.sync.aligned.m8n8.x4.trans.shared.b16 {%0,%1,%2,%3}, [%4];"
                 : "=r"(r[0]), "=r"(r[1]), "=r"(r[2]), "=r"(r[3]) : "r"(a));
}
__device__ __forceinline__ void mma_bf16(float* c, const unsigned* a, const unsigned* b) {
    asm volatile(
        "mma.sync.aligned.m16n8k16.row.col.f32.bf16.bf16.f32 "
        "{%0,%1,%2,%3},{%4,%5,%6,%7},{%8,%9},{%0,%1,%2,%3};"
        : "+f"(c[0]), "+f"(c[1]), "+f"(c[2]), "+f"(c[3])
        : "r"(a[0]), "r"(a[1]), "r"(a[2]), "r"(a[3]), "r"(b[0]), "r"(b[1]));
}
__device__ __forceinline__ void split_pair(float x, float y,
                                           __nv_bfloat162& h2, __nv_bfloat162& l2) {
    __nv_bfloat16 hx = __float2bfloat16_rn(x);
    __nv_bfloat16 hy = __float2bfloat16_rn(y);
    __nv_bfloat16 lx = __float2bfloat16_rn(x - __bfloat162float(hx));
    __nv_bfloat16 ly = __float2bfloat16_rn(y - __bfloat162float(hy));
    h2 = __halves2bfloat162(hx, hy);
    l2 = __halves2bfloat162(lx, ly);
}
__device__ __forceinline__ void cp16(unsigned dst, const void* src) {
    asm volatile("cp.async.cg.shared.global [%0], [%1], 16;" :: "r"(dst), "l"(src));
}
__device__ __forceinline__ void cp_commit() {
    asm volatile("cp.async.commit_group;");
}
__device__ __forceinline__ void cp_wait0() {
    asm volatile("cp.async.wait_group 0;");
}
__device__ __forceinline__ void cp_wait1() {
    asm volatile("cp.async.wait_group 1;");
}

// ---------------------------------------------------------------------------
// Split fp32 tensor into bf16 hi/lo pair.
// ---------------------------------------------------------------------------
__global__ __launch_bounds__(256) void split_f32(
    const float* __restrict__ in, __nv_bfloat16* __restrict__ hi,
    __nv_bfloat16* __restrict__ lo, int n4)
{
    int i = blockIdx.x * blockDim.x + threadIdx.x;
    if (i < n4) {
        float4 v = ((const float4*)in)[i];
        __nv_bfloat162 h2, l2, h3, l3;
        split_pair(v.x, v.y, h2, l2);
        split_pair(v.z, v.w, h3, l3);
        ((__nv_bfloat162*)hi)[i * 2]     = h2;
        ((__nv_bfloat162*)hi)[i * 2 + 1] = h3;
        ((__nv_bfloat162*)lo)[i * 2]     = l2;
        ((__nv_bfloat162*)lo)[i * 2 + 1] = l3;
    }
}

// ---------------------------------------------------------------------------
// Scores: per (b,h) 128x64 tile of q @ k^T * 0.125, masked, fp32 to attn.
// Emits per-(row, tile) max and exp-sum. Epilogue restaged through smem for
// fully coalesced mask/STG + shfl row stats.
// ---------------------------------------------------------------------------
#define SC_QH 0
#define SC_QL 18432
#define SC_KH 36864
#define SC_KL 46080
#define SC_SMEM 55296

__global__ __launch_bounds__(256, 3) void mma_scores(
    const unsigned char* __restrict__ mask, float* __restrict__ attn)
{
    extern __shared__ __align__(16) char smem_raw[];
    __nv_bfloat16 (*Qh)[72] = (__nv_bfloat16(*)[72])(smem_raw + SC_QH);
    __nv_bfloat16 (*Ql)[72] = (__nv_bfloat16(*)[72])(smem_raw + SC_QL);
    __nv_bfloat16 (*Kh)[72] = (__nv_bfloat16(*)[72])(smem_raw + SC_KH);
    __nv_bfloat16 (*Kl)[72] = (__nv_bfloat16(*)[72])(smem_raw + SC_KL);

    const int t = threadIdx.x, lane = t & 31, w = t >> 5;
    const int wm = w & 3, wn = w >> 2;
    const int bh = blockIdx.z, b = bh >> 3;
    const int r0 = blockIdx.y * 128, c0 = blockIdx.x * 64;
    const size_t base = (size_t)bh * SS * DK;

    #pragma unroll
    for (int i = 0; i < 12; i++) {
        int ch = t + i * 256;
        if (ch < 1024) {
            int r = ch >> 3, c8 = (ch & 7) * 8;
            cp16(sptr(&Qh[r][c8]), g_qh + base + (size_t)(r0 + r) * 64 + c8);
        } else if (ch < 2048) {
            int idx = ch - 1024, r = idx >> 3, c8 = (idx & 7) * 8;
            cp16(sptr(&Ql[r][c8]), g_ql + base + (size_t)(r0 + r) * 64 + c8);
        } else if (ch < 2560) {
            int idx = ch - 2048, r = idx >> 3, c8 = (idx & 7) * 8;
            cp16(sptr(&Kh[r][c8]), g_kh + base + (size_t)(c0 + r) * 64 + c8);
        } else {
            int idx = ch - 2560, r = idx >> 3, c8 = (idx & 7) * 8;
            cp16(sptr(&Kl[r][c8]), g_kl + base + (size_t)(c0 + r) * 64 + c8);
        }
    }
    cp_commit();
    cp_wait0();
    __syncthreads();

    float acc[2][4][4] = {};
    #pragma unroll
    for (int k2 = 0; k2 < 64; k2 += 16) {
        unsigned ah[2][4], al[2][4];
        #pragma unroll
        for (int mi = 0; mi < 2; mi++) {
            int r = wm * 32 + mi * 16 + (lane & 15);
            int c = k2 + ((lane >> 4) << 3);
            ldsm4(ah[mi], sptr(&Qh[r][c]));
            ldsm4(al[mi], sptr(&Ql[r][c]));
        }
        #pragma unroll
        for (int g = 0; g < 2; g++) {
            int nr = wn * 32 + g * 16 + (lane & 7) + ((lane >> 4) << 3);
            int kc = k2 + (((lane >> 3) & 1) << 3);
            unsigned bh_[4], bl_[4];
            ldsm4(bh_, sptr(&Kh[nr][kc]));
            ldsm4(bl_, sptr(&Kl[nr][kc]));
            #pragma unroll
            for (int mi = 0; mi < 2; mi++) {
                mma_bf16(acc[mi][2*g],   ah[mi], &bh_[0]);
                mma_bf16(acc[mi][2*g+1], ah[mi], &bh_[2]);
                mma_bf16(acc[mi][2*g],   ah[mi], &bl_[0]);
                mma_bf16(acc[mi][2*g+1], ah[mi], &bl_[2]);
                mma_bf16(acc[mi][2*g],   al[mi], &bh_[0]);
                mma_bf16(acc[mi][2*g+1], al[mi], &bh_[2]);
            }
        }
    }

    // ---- restage through smem: [128][68] fp32, halves at col offsets 0/34
    __syncthreads();
    float* stg = (float*)smem_raw;
    #pragma unroll
    for (int mi = 0; mi < 2; mi++) {
        #pragma unroll
        for (int nf = 0; nf < 4; nf++) {
            float* c = acc[mi][nf];
            int r = wm * 32 + mi * 16 + (lane >> 2);
            int cc = wn * 34 + nf * 8 + (lane & 3) * 2;
            *(float2*)&stg[r * 68 + cc]       = make_float2(c[0], c[1]);
            *(float2*)&stg[(r + 8) * 68 + cc] = make_float2(c[2], c[3]);
        }
    }
    __syncthreads();

    // coalesced readback: warp w -> rows w*16..+15; lane -> cols lane*2..+1
    {
        const int colg = lane * 2;
        const int colp = colg + (lane >= 16 ? 2 : 0);
        #pragma unroll 4
        for (int r = 0; r < 16; r++) {
            int row = w * 16 + r;
            float2 v = *(float2*)&stg[row * 68 + colp];
            size_t gr = (size_t)(r0 + row);
            const unsigned char* mp = mask + ((size_t)b * SS + gr) * SS + c0 + colg;
            v.x = mp[0] ? -1e9f : v.x * 0.125f;
            v.y = mp[1] ? -1e9f : v.y * 0.125f;
            *(float2*)(attn + ((size_t)bh * SS + gr) * SS + c0 + colg) = v;
            float mx = fmaxf(v.x, v.y);
            #pragma unroll
            for (int o = 16; o; o >>= 1) mx = fmaxf(mx, __shfl_xor_sync(0xffffffffu, mx, o));
            float s = __expf(v.x - mx) + __expf(v.y - mx);
            #pragma unroll
            for (int o = 16; o; o >>= 1) s += __shfl_xor_sync(0xffffffffu, s, o);
            if (lane == 0) {
                size_t idx = ((size_t)bh * SS + gr) * NCT + blockIdx.x;
                g_smax[idx] = mx;
                g_ssum[idx] = s;
            }
        }
    }
}

// ---------------------------------------------------------------------------
// Combine tile stats into per-row max and 1/sum. One warp per row.
// ---------------------------------------------------------------------------
__global__ __launch_bounds__(256) void softmax_stats(
    float* __restrict__ rowm, float* __restrict__ rinv)
{
    const int w = threadIdx.x >> 5, lane = threadIdx.x & 31;
    const size_t rg = (size_t)blockIdx.x * 8 + w;
    float m_l = g_smax[rg * NCT + lane];
    float s_l = g_ssum[rg * NCT + lane];
    float m = m_l;
    #pragma unroll
    for (int o = 16; o; o >>= 1) m = fmaxf(m, __shfl_xor_sync(0xffffffffu, m, o));
    float c = __expf(m_l - m) * s_l;
    #pragma unroll
    for (int o = 16; o; o >>= 1) c += __shfl_xor_sync(0xffffffffu, c, o);
    if (lane == 0) { rowm[rg] = m; rinv[rg] = 1.0f / c; }
}

// ---------------------------------------------------------------------------
// GEMM on pre-split bf16 operands: C = A[M,512] @ W[512,512] + bias (+resid)
// Block 128x64, 256 thr, 8 warps (4m x 2n), warp 32x32, K-step 32,
// double-buffered cp.async pipeline, 3 CTAs/SM.
// ---------------------------------------------------------------------------
#define GB_AH 0
#define GB_AL 20480
#define GB_WH 40960
#define GB_WL 50176
#define GB_SMEM 59392
#define GB_ABUF 10240
#define GB_WBUF 4608

__device__ __forceinline__ void gload(
    unsigned sb, int buf,
    const __nv_bfloat16* __restrict__ Ah, const __nv_bfloat16* __restrict__ Al,
    const __nv_bfloat16* __restrict__ Wh, const __nv_bfloat16* __restrict__ Wl,
    int row0, int col0, int kk, int t)
{
    #pragma unroll
    for (int i = 0; i < 2; i++) {
        int ch = t + i * 256;
        int r = ch >> 2, c = (ch & 3) * 8;
        unsigned off = buf * GB_ABUF + r * 80 + c * 2;
        cp16(sb + GB_AH + off, Ah + (size_t)(row0 + r) * 512 + kk + c);
        cp16(sb + GB_AL + off, Al + (size_t)(row0 + r) * 512 + kk + c);
    }
    {
        int r = t >> 3, c = (t & 7) * 8;
        unsigned off = buf * GB_WBUF + r * 144 + c * 2;
        cp16(sb + GB_WH + off, Wh + (size_t)(kk + r) * 512 + col0 + c);
        cp16(sb + GB_WL + off, Wl + (size_t)(kk + r) * 512 + col0 + c);
    }
}

template<int OUTPROJ>
__global__ __launch_bounds__(256, 3) void mma_gemm512(
    const __nv_bfloat16* __restrict__ Ah, const __nv_bfloat16* __restrict__ Al,
    const __nv_bfloat16* __restrict__ Wh, const __nv_bfloat16* __restrict__ Wl,
    const float* __restrict__ bias, const float* __restrict__ resid,
    __nv_bfloat16* __restrict__ Oh, __nv_bfloat16* __restrict__ Ol,
    float* __restrict__ Of)
{
    extern __shared__ __align__(16) char smem_raw[];
    const unsigned sb = sptr(smem_raw);
    const int t = threadIdx.x, lane = t & 31, w = t >> 5;
    const int wm = w & 3, wn = w >> 2;
    const int row0 = blockIdx.y * 128, col0 = blockIdx.x * 64;

    float acc[2][4][4] = {};

    gload(sb, 0, Ah, Al, Wh, Wl, row0, col0, 0, t);
    cp_commit();

    for (int it = 0; it < 16; it++) {
        if (it < 15)
            gload(sb, (it + 1) & 1, Ah, Al, Wh, Wl, row0, col0, (it + 1) * 32, t);
        cp_commit();
        cp_wait1();
        __syncthreads();

        const unsigned abh = sb + GB_AH + (it & 1) * GB_ABUF;
        const unsigned abl = sb + GB_AL + (it & 1) * GB_ABUF;
        const unsigned wbh = sb + GB_WH + (it & 1) * GB_WBUF;
        const unsigned wbl = sb + GB_WL + (it & 1) * GB_WBUF;

        #pragma unroll
        for (int k2 = 0; k2 < 32; k2 += 16) {
            unsigned ah[2][4], al[2][4];
            #pragma unroll
            for (int mi = 0; mi < 2; mi++) {
                int r = wm * 32 + mi * 16 + (lane & 15);
                int c = k2 + ((lane >> 4) << 3);
                ldsm4(ah[mi], abh + r * 80 + c * 2);
                ldsm4(al[mi], abl + r * 80 + c * 2);
            }
            #pragma unroll
            for (int g = 0; g < 2; g++) {
                int kr = k2 + (lane & 7) + (((lane >> 3) & 1) << 3);
                int nc = wn * 32 + g * 16 + ((lane >> 4) << 3);
                unsigned bh_[4], bl_[4];
                ldsm4t(bh_, wbh + kr * 144 + nc * 2);
                ldsm4t(bl_, wbl + kr * 144 + nc * 2);
                #pragma unroll
                for (int mi = 0; mi < 2; mi++) {
                    mma_bf16(acc[mi][2*g],   ah[mi], &bh_[0]);
                    mma_bf16(acc[mi][2*g+1], ah[mi], &bh_[2]);
                    mma_bf16(acc[mi][2*g],   ah[mi], &bl_[0]);
                    mma_bf16(acc[mi][2*g+1], ah[mi], &bl_[2]);
                    mma_bf16(acc[mi][2*g],   al[mi], &bh_[0]);
                    mma_bf16(acc[mi][2*g+1], al[mi], &bh_[2]);
                }
            }
        }
        __syncthreads();
    }

    #pragma unroll
    for (int mi = 0; mi < 2; mi++) {
        #pragma unroll
        for (int nf = 0; nf < 4; nf++) {
            float* c = acc[mi][nf];
            int m = row0 + wm * 32 + mi * 16 + (lane >> 2);
            int n = col0 + wn * 32 + nf * 8 + ((lane & 3) << 1);
            float b0 = bias[n], b1 = bias[n + 1];
            if (OUTPROJ) {
                float2 r = *(const float2*)(resid + (size_t)m * 512 + n);
                *(float2*)(Of + (size_t)m * 512 + n) =
                    make_float2(c[0] + b0 + r.x, c[1] + b1 + r.y);
                r = *(const float2*)(resid + (size_t)(m + 8) * 512 + n);
                *(float2*)(Of + (size_t)(m + 8) * 512 + n) =
                    make_float2(c[2] + b0 + r.x, c[3] + b1 + r.y);
            } else {
                int h = n >> 6, d = n & 63;
                int b = m >> 11, s = m & 2047;
                __nv_bfloat162 h2, l2;
                size_t base = ((size_t)(b * NH + h) * SS + s) * DK + d;
                split_pair(c[0] + b0, c[1] + b1, h2, l2);
                *(__nv_bfloat162*)&Oh[base] = h2;
                *(__nv_bfloat162*)&Ol[base] = l2;
                base += 8 * (size_t)DK;
                split_pair(c[2] + b0, c[3] + b1, h2, l2);
                *(__nv_bfloat162*)&Oh[base] = h2;
                *(__nv_bfloat162*)&Ol[base] = l2;
            }
        }
    }
}

// ---------------------------------------------------------------------------
// Context + softmax normalize: reads raw scores, writes probs in-place,
// accumulates ctx = P @ V, writes ctx as bf16 hi/lo. (256,2): see round-6.
// ---------------------------------------------------------------------------
__global__ __launch_bounds__(256, 2) void mma_context(
    float* __restrict__ attn, const float* __restrict__ rowm,
    const float* __restrict__ rinv,
    __nv_bfloat16* __restrict__ ctxh, __nv_bfloat16* __restrict__ ctxl)
{
    __shared__ __align__(16) __nv_bfloat16 Ph[128][72], Pl[128][72];
    __shared__ __align__(16) __nv_bfloat16 Vh[64][72],  Vl[64][72];
    const int t = threadIdx.x, lane = t & 31, w = t >> 5;
    const int wm = w & 3, wn = w >> 2;
    const int bh = blockIdx.y, r0 = blockIdx.x * 128;
    const size_t vbase = (size_t)bh * SS * DK;

    const int pr = t >> 1, pc = (t & 1) * 32;
    const float rm = __ldg(rowm + (size_t)bh * SS + r0 + pr);
    const float ri = __ldg(rinv + (size_t)bh * SS + r0 + pr);
    float* prow = attn + (size_t)bh * SS * SS + (size_t)(r0 + pr) * SS + pc;

    float acc[2][4][4] = {};

    for (int kk = 0; kk < SS; kk += 64) {
        #pragma unroll
        for (int i = 0; i < 4; i++) {
            int chunk = t + i * 256;
            int arr = chunk >> 9, idx = chunk & 511;
            int vr = idx >> 3, vc = (idx & 7) * 8;
            if (arr == 0)
                cp16(sptr(&Vh[vr][vc]), g_vh + vbase + (size_t)(kk + vr) * 64 + vc);
            else
                cp16(sptr(&Vl[vr][vc]), g_vl + vbase + (size_t)(kk + vr) * 64 + vc);
        }
        {
            float* p = prow + kk;
            #pragma unroll
            for (int i = 0; i < 32; i += 4) {
                float4 v = *(float4*)(p + i);
                v.x = __expf(v.x - rm) * ri;
                v.y = __expf(v.y - rm) * ri;
                v.z = __expf(v.z - rm) * ri;
                v.w = __expf(v.w - rm) * ri;
                *(float4*)(p + i) = v;               // final attn probabilities
                __nv_bfloat162 h2, l2;
                split_pair(v.x, v.y, h2, l2);
                *(__nv_bfloat162*)&Ph[pr][pc + i]     = h2;
                *(__nv_bfloat162*)&Pl[pr][pc + i]     = l2;
                split_pair(v.z, v.w, h2, l2);
                *(__nv_bfloat162*)&Ph[pr][pc + i + 2] = h2;
                *(__nv_bfloat162*)&Pl[pr][pc + i + 2] = l2;
            }
        }
        cp_commit();
        cp_wait0();
        __syncthreads();
        #pragma unroll
        for (int k2 = 0; k2 < 64; k2 += 16) {
            unsigned ah[2][4], al[2][4];
            #pragma unroll
            for (int mi = 0; mi < 2; mi++) {
                int r = wm * 32 + mi * 16 + (lane & 15);
                int c = k2 + ((lane >> 4) << 3);
                ldsm4(ah[mi], sptr(&Ph[r][c]));
                ldsm4(al[mi], sptr(&Pl[r][c]));
            }
            #pragma unroll
            for (int g = 0; g < 2; g++) {
                int kr = k2 + (lane & 7) + (((lane >> 3) & 1) << 3);
                int nc = wn * 32 + g * 16 + ((lane >> 4) << 3);
                unsigned bh_[4], bl_[4];
                ldsm4t(bh_, sptr(&Vh[kr][nc]));
                ldsm4t(bl_, sptr(&Vl[kr][nc]));
                #pragma unroll
                for (int mi = 0; mi < 2; mi++) {
                    mma_bf16(acc[mi][2*g],   ah[mi], &bh_[0]);
                    mma_bf16(acc[mi][2*g+1], ah[mi], &bh_[2]);
                    mma_bf16(acc[mi][2*g],   ah[mi], &bl_[0]);
                    mma_bf16(acc[mi][2*g+1], ah[mi], &bl_[2]);
                    mma_bf16(acc[mi][2*g],   al[mi], &bh_[0]);
                    mma_bf16(acc[mi][2*g+1], al[mi], &bh_[2]);
                }
            }
        }
        __syncthreads();
    }

    const int b = bh >> 3, h = bh & 7;
    #pragma unroll
    for (int mi = 0; mi < 2; mi++) {
        #pragma unroll
        for (int nf = 0; nf < 4; nf++) {
            float* c = acc[mi][nf];
            int m = r0 + wm * 32 + mi * 16 + (lane >> 2);
            int n = wn * 32 + nf * 8 + ((lane & 3) << 1);
            __nv_bfloat162 h2, l2;
            size_t idx = ((size_t)(b * SS + m)) * EMB + h * DK + n;
            split_pair(c[0], c[1], h2, l2);
            *(__nv_bfloat162*)&ctxh[idx] = h2;
            *(__nv_bfloat162*)&ctxl[idx] = l2;
            idx += 8 * (size_t)EMB;
            split_pair(c[2], c[3], h2, l2);
            *(__nv_bfloat162*)&ctxh[idx] = h2;
            *(__nv_bfloat162*)&ctxl[idx] = l2;
        }
    }
}

// ---------------------------------------------------------------------------
// LayerNorm over 512.
// ---------------------------------------------------------------------------
__global__ __launch_bounds__(128) void ln_kernel(
    const float* __restrict__ gamma, const float* __restrict__ beta,
    float* __restrict__ out)
{
    const size_t row = blockIdx.x;
    const int t = threadIdx.x;
    const float* x = g_x + row * EMB;
    __shared__ float rs[4], rq[4];

    float4 v = ((const float4*)x)[t];
    float s  = v.x + v.y + v.z + v.w;
    float sq = v.x*v.x + v.y*v.y + v.z*v.z + v.w*v.w;
    #pragma unroll
    for (int o = 16; o; o >>= 1) {
        s  += __shfl_xor_sync(0xffffffffu, s,  o);
        sq += __shfl_xor_sync(0xffffffffu, sq, o);
    }
    if ((t & 31) == 0) { rs[t >> 5] = s; rq[t >> 5] = sq; }
    __syncthreads();
    s  = rs[0] + rs[1] + rs[2] + rs[3];
    sq = rq[0] + rq[1] + rq[2] + rq[3];

    float mu  = s * (1.0f / 512.0f);
    float var = sq * (1.0f / 512.0f) - mu * mu;
    float inv = rsqrtf(var + 1e-5f);

    float4 g = ((const float4*)gamma)[t];
    float4 bb = ((const float4*)beta)[t];
    float4 o;
    o.x = (v.x - mu) * inv * g.x + bb.x;
    o.y = (v.y - mu) * inv * g.y + bb.y;
    o.z = (v.z - mu) * inv * g.z + bb.z;
    o.w = (v.w - mu) * inv * g.w + bb.w;
    ((float4*)(out + row * EMB))[t] = o;
}

// ---------------------------------------------------------------------------
extern "C" void kernel_launch(void* const* d_in, const int* in_sizes, int n_in,
                              void* d_out, int out_size)
{
    const float* Q  = (const float*)d_in[0];
    const float* K  = (const float*)d_in[1];
    const float* V  = (const float*)d_in[2];
    const unsigned char* mask = (const unsigned char*)d_in[3];
    const float* Wq = (const float*)d_in[4];
    const float* bq = (const float*)d_in[5];
    const float* Wk = (const float*)d_in[6];
    const float* bk = (const float*)d_in[7];
    const float* Wv = (const float*)d_in[8];
    const float* bv = (const float*)d_in[9];
    const float* Wo = (const float*)d_in[10];
    const float* bo = (const float*)d_in[11];
    const float* gamma = (const float*)d_in[12];
    const float* beta  = (const float*)d_in[13];

    float* out  = (float*)d_out;
    float* attn = out + (size_t)BSROWS * EMB;

    __nv_bfloat16 *qh, *ql, *kh, *kl, *vh, *vl;
    __nv_bfloat16 *inqh, *inql, *inkh, *inkl, *invh, *invl;
    __nv_bfloat16 *wqh, *wql, *wkh, *wkl, *wvh, *wvl, *woh, *wol;
    __nv_bfloat16 *ctxh, *ctxl;
    float *xp, *rowmp, *rinvp;
    cudaGetSymbolAddress((void**)&qh, g_qh);
    cudaGetSymbolAddress((void**)&ql, g_ql);
    cudaGetSymbolAddress((void**)&kh, g_kh);
    cudaGetSymbolAddress((void**)&kl, g_kl);
    cudaGetSymbolAddress((void**)&vh, g_vh);
    cudaGetSymbolAddress((void**)&vl, g_vl);
    cudaGetSymbolAddress((void**)&inqh, g_inqh);
    cudaGetSymbolAddress((void**)&inql, g_inql);
    cudaGetSymbolAddress((void**)&inkh, g_inkh);
    cudaGetSymbolAddress((void**)&inkl, g_inkl);
    cudaGetSymbolAddress((void**)&invh, g_invh);
    cudaGetSymbolAddress((void**)&invl, g_invl);
    cudaGetSymbolAddress((void**)&wqh, g_wqh);
    cudaGetSymbolAddress((void**)&wql, g_wql);
    cudaGetSymbolAddress((void**)&wkh, g_wkh);
    cudaGetSymbolAddress((void**)&wkl, g_wkl);
    cudaGetSymbolAddress((void**)&wvh, g_wvh);
    cudaGetSymbolAddress((void**)&wvl, g_wvl);
    cudaGetSymbolAddress((void**)&woh, g_woh);
    cudaGetSymbolAddress((void**)&wol, g_wol);
    cudaGetSymbolAddress((void**)&ctxh, g_ctxh);
    cudaGetSymbolAddress((void**)&ctxl, g_ctxl);
    cudaGetSymbolAddress((void**)&xp,   g_x);
    cudaGetSymbolAddress((void**)&rowmp, g_rowm);
    cudaGetSymbolAddress((void**)&rinvp, g_rinv);

    cudaFuncSetAttribute(mma_scores, cudaFuncAttributeMaxDynamicSharedMemorySize,
                         SC_SMEM);
    cudaFuncSetAttribute(mma_gemm512<0>, cudaFuncAttributeMaxDynamicSharedMemorySize,
                         GB_SMEM);
    cudaFuncSetAttribute(mma_gemm512<1>, cudaFuncAttributeMaxDynamicSharedMemorySize,
                         GB_SMEM);

    // pre-split inputs + weights
    const int n4_in = BSROWS * EMB / 4;       // 1,048,576
    const int n4_w  = EMB * EMB / 4;          // 65,536
    split_f32<<<n4_in / 256, 256>>>(Q, inqh, inql, n4_in);
    split_f32<<<n4_in / 256, 256>>>(K, inkh, inkl, n4_in);
    split_f32<<<n4_in / 256, 256>>>(V, invh, invl, n4_in);
    split_f32<<<n4_w / 256, 256>>>(Wq, wqh, wql, n4_w);
    split_f32<<<n4_w / 256, 256>>>(Wk, wkh, wkl, n4_w);
    split_f32<<<n4_w / 256, 256>>>(Wv, wvh, wvl, n4_w);
    split_f32<<<n4_w / 256, 256>>>(Wo, woh, wol, n4_w);

    dim3 gemm_grid(EMB / 64, BSROWS / 128);        // 8 x 64
    mma_gemm512<0><<<gemm_grid, 256, GB_SMEM>>>(inqh, inql, wqh, wql, bq,
                                                nullptr, qh, ql, nullptr);
    mma_gemm512<0><<<gemm_grid, 256, GB_SMEM>>>(inkh, inkl, wkh, wkl, bk,
                                                nullptr, kh, kl, nullptr);
    mma_gemm512<0><<<gemm_grid, 256, GB_SMEM>>>(invh, invl, wvh, wvl, bv,
                                                nullptr, vh, vl, nullptr);

    dim3 sc_grid(SS / 64, SS / 128, BH);           // 32 x 16 x 32
    mma_scores<<<sc_grid, 256, SC_SMEM>>>(mask, attn);

    softmax_stats<<<(BH * SS) / 8, 256>>>(rowmp, rinvp);

    dim3 ctx_grid(SS / 128, BH);                   // 16 x 32
    mma_context<<<ctx_grid, 256>>>(attn, rowmp, rinvp, ctxh, ctxl);

    mma_gemm512<1><<<gemm_grid, 256, GB_SMEM>>>(ctxh, ctxl, woh, wol, bo,
                                                Q, nullptr, nullptr, xp);

    ln_kernel<<<BSROWS, 128>>>(gamma, beta, out);
}

// round 10
// speedup vs baseline: 3.1779x; 1.1207x over previous
#include <cuda_runtime.h>
#include <cuda_bf16.h>
#include <math.h>

#define BB   4
#define SS   2048
#define EMB  512
#define NH   8
#define DK   64
#define BSROWS (BB*SS)   // 8192
#define BH   (BB*NH)     // 32
#define NCT  (SS/64)     // 32 col tiles in scores

// projection outputs
__device__ __nv_bfloat16 g_qh[BH * SS * DK];
__device__ __nv_bfloat16 g_ql[BH * SS * DK];
__device__ __nv_bfloat16 g_kh[BH * SS * DK];
__device__ __nv_bfloat16 g_kl[BH * SS * DK];
__device__ __nv_bfloat16 g_vh[BH * SS * DK];       // plain bf16 (precision budget)
// pre-split / pre-converted inputs
__device__ __nv_bfloat16 g_inqh[BSROWS * EMB], g_inql[BSROWS * EMB];
__device__ __nv_bfloat16 g_inkh[BSROWS * EMB], g_inkl[BSROWS * EMB];
__device__ __nv_bfloat16 g_invh[BSROWS * EMB];
// weights
__device__ __nv_bfloat16 g_wqh[EMB * EMB], g_wql[EMB * EMB];
__device__ __nv_bfloat16 g_wkh[EMB * EMB], g_wkl[EMB * EMB];
__device__ __nv_bfloat16 g_wvh[EMB * EMB];
__device__ __nv_bfloat16 g_woh[EMB * EMB];
// context (plain bf16) + pre-LN sum
__device__ __nv_bfloat16 g_ctxh[BSROWS * EMB];
__device__ float g_x[BSROWS * EMB];
// softmax stats
__device__ float g_smax[(size_t)BH * SS * NCT];
__device__ float g_ssum[(size_t)BH * SS * NCT];
__device__ float g_rowm[(size_t)BH * SS];
__device__ float g_rinv[(size_t)BH * SS];

// ---------------------------------------------------------------------------
// helpers
// ---------------------------------------------------------------------------
__device__ __forceinline__ unsigned sptr(const void* p) {
    return (unsigned)__cvta_generic_to_shared(p);
}
__device__ __forceinline__ void ldsm4(unsigned* r, unsigned a) {
    asm volatile("ldmatrix.sync.aligned.m8n8.x4.shared.b16 {%0,%1,%2,%3}, [%4];"
                 : "=r"(r[0]), "=r"(r[1]), "=r"(r[2]), "=r"(r[3]) : "r"(a));
}
__device__ __forceinline__ void ldsm4t(unsigned* r, unsigned a) {
    asm volatile("ldmatrix.sync.aligned.m8n8.x4.trans.shared.b16 {%0,%1,%2,%3}, [%4];"
                 : "=r"(r[0]), "=r"(r[1]), "=r"(r[2]), "=r"(r[3]) : "r"(a));
}
__device__ __forceinline__ void mma_bf16(float* c, const unsigned* a, const unsigned* b) {
    asm volatile(
        "mma.sync.aligned.m16n8k16.row.col.f32.bf16.bf16.f32 "
        "{%0,%1,%2,%3},{%4,%5,%6,%7},{%8,%9},{%0,%1,%2,%3};"
        : "+f"(c[0]), "+f"(c[1]), "+f"(c[2]), "+f"(c[3])
        : "r"(a[0]), "r"(a[1]), "r"(a[2]), "r"(a[3]), "r"(b[0]), "r"(b[1]));
}
__device__ __forceinline__ void split_pair(float x, float y,
                                           __nv_bfloat162& h2, __nv_bfloat162& l2) {
    __nv_bfloat16 hx = __float2bfloat16_rn(x);
    __nv_bfloat16 hy = __float2bfloat16_rn(y);
    __nv_bfloat16 lx = __float2bfloat16_rn(x - __bfloat162float(hx));
    __nv_bfloat16 ly = __float2bfloat16_rn(y - __bfloat162float(hy));
    h2 = __halves2bfloat162(hx, hy);
    l2 = __halves2bfloat162(lx, ly);
}
__device__ __forceinline__ void cp16(unsigned dst, const void* src) {
    asm volatile("cp.async.cg.shared.global [%0], [%1], 16;" :: "r"(dst), "l"(src));
}
__device__ __forceinline__ void cp_commit() {
    asm volatile("cp.async.commit_group;");
}
__device__ __forceinline__ void cp_wait0() {
    asm volatile("cp.async.wait_group 0;");
}
__device__ __forceinline__ void cp_wait1() {
    asm volatile("cp.async.wait_group 1;");
}

// ---------------------------------------------------------------------------
// Split fp32 into bf16 hi/lo; and hi-only convert.
// ---------------------------------------------------------------------------
__global__ __launch_bounds__(256) void split_f32(
    const float* __restrict__ in, __nv_bfloat16* __restrict__ hi,
    __nv_bfloat16* __restrict__ lo, int n4)
{
    int i = blockIdx.x * blockDim.x + threadIdx.x;
    if (i < n4) {
        float4 v = ((const float4*)in)[i];
        __nv_bfloat162 h2, l2, h3, l3;
        split_pair(v.x, v.y, h2, l2);
        split_pair(v.z, v.w, h3, l3);
        ((__nv_bfloat162*)hi)[i * 2]     = h2;
        ((__nv_bfloat162*)hi)[i * 2 + 1] = h3;
        ((__nv_bfloat162*)lo)[i * 2]     = l2;
        ((__nv_bfloat162*)lo)[i * 2 + 1] = l3;
    }
}

__global__ __launch_bounds__(256) void tobf16_f32(
    const float* __restrict__ in, __nv_bfloat16* __restrict__ hi, int n4)
{
    int i = blockIdx.x * blockDim.x + threadIdx.x;
    if (i < n4) {
        float4 v = ((const float4*)in)[i];
        ((__nv_bfloat162*)hi)[i * 2]     = __float22bfloat162_rn(make_float2(v.x, v.y));
        ((__nv_bfloat162*)hi)[i * 2 + 1] = __float22bfloat162_rn(make_float2(v.z, v.w));
    }
}

// ---------------------------------------------------------------------------
// Scores: per (b,h) 128x64 tile of q @ k^T * 0.125, masked, fp32 to attn.
// Split (3-product) MMA; coalesced smem-restaged epilogue + row stats.
// ---------------------------------------------------------------------------
#define SC_QH 0
#define SC_QL 18432
#define SC_KH 36864
#define SC_KL 46080
#define SC_SMEM 55296

__global__ __launch_bounds__(256, 3) void mma_scores(
    const unsigned char* __restrict__ mask, float* __restrict__ attn)
{
    extern __shared__ __align__(16) char smem_raw[];
    __nv_bfloat16 (*Qh)[72] = (__nv_bfloat16(*)[72])(smem_raw + SC_QH);
    __nv_bfloat16 (*Ql)[72] = (__nv_bfloat16(*)[72])(smem_raw + SC_QL);
    __nv_bfloat16 (*Kh)[72] = (__nv_bfloat16(*)[72])(smem_raw + SC_KH);
    __nv_bfloat16 (*Kl)[72] = (__nv_bfloat16(*)[72])(smem_raw + SC_KL);

    const int t = threadIdx.x, lane = t & 31, w = t >> 5;
    const int wm = w & 3, wn = w >> 2;
    const int bh = blockIdx.z, b = bh >> 3;
    const int r0 = blockIdx.y * 128, c0 = blockIdx.x * 64;
    const size_t base = (size_t)bh * SS * DK;

    #pragma unroll
    for (int i = 0; i < 12; i++) {
        int ch = t + i * 256;
        if (ch < 1024) {
            int r = ch >> 3, c8 = (ch & 7) * 8;
            cp16(sptr(&Qh[r][c8]), g_qh + base + (size_t)(r0 + r) * 64 + c8);
        } else if (ch < 2048) {
            int idx = ch - 1024, r = idx >> 3, c8 = (idx & 7) * 8;
            cp16(sptr(&Ql[r][c8]), g_ql + base + (size_t)(r0 + r) * 64 + c8);
        } else if (ch < 2560) {
            int idx = ch - 2048, r = idx >> 3, c8 = (idx & 7) * 8;
            cp16(sptr(&Kh[r][c8]), g_kh + base + (size_t)(c0 + r) * 64 + c8);
        } else {
            int idx = ch - 2560, r = idx >> 3, c8 = (idx & 7) * 8;
            cp16(sptr(&Kl[r][c8]), g_kl + base + (size_t)(c0 + r) * 64 + c8);
        }
    }
    cp_commit();
    cp_wait0();
    __syncthreads();

    float acc[2][4][4] = {};
    #pragma unroll
    for (int k2 = 0; k2 < 64; k2 += 16) {
        unsigned ah[2][4], al[2][4];
        #pragma unroll
        for (int mi = 0; mi < 2; mi++) {
            int r = wm * 32 + mi * 16 + (lane & 15);
            int c = k2 + ((lane >> 4) << 3);
            ldsm4(ah[mi], sptr(&Qh[r][c]));
            ldsm4(al[mi], sptr(&Ql[r][c]));
        }
        #pragma unroll
        for (int g = 0; g < 2; g++) {
            int nr = wn * 32 + g * 16 + (lane & 7) + ((lane >> 4) << 3);
            int kc = k2 + (((lane >> 3) & 1) << 3);
            unsigned bh_[4], bl_[4];
            ldsm4(bh_, sptr(&Kh[nr][kc]));
            ldsm4(bl_, sptr(&Kl[nr][kc]));
            #pragma unroll
            for (int mi = 0; mi < 2; mi++) {
                mma_bf16(acc[mi][2*g],   ah[mi], &bh_[0]);
                mma_bf16(acc[mi][2*g+1], ah[mi], &bh_[2]);
                mma_bf16(acc[mi][2*g],   ah[mi], &bl_[0]);
                mma_bf16(acc[mi][2*g+1], ah[mi], &bl_[2]);
                mma_bf16(acc[mi][2*g],   al[mi], &bh_[0]);
                mma_bf16(acc[mi][2*g+1], al[mi], &bh_[2]);
            }
        }
    }

    // restage through smem: [128][68] fp32, halves at col offsets 0/34
    __syncthreads();
    float* stg = (float*)smem_raw;
    #pragma unroll
    for (int mi = 0; mi < 2; mi++) {
        #pragma unroll
        for (int nf = 0; nf < 4; nf++) {
            float* c = acc[mi][nf];
            int r = wm * 32 + mi * 16 + (lane >> 2);
            int cc = wn * 34 + nf * 8 + (lane & 3) * 2;
            *(float2*)&stg[r * 68 + cc]       = make_float2(c[0], c[1]);
            *(float2*)&stg[(r + 8) * 68 + cc] = make_float2(c[2], c[3]);
        }
    }
    __syncthreads();

    {
        const int colg = lane * 2;
        const int colp = colg + (lane >= 16 ? 2 : 0);
        #pragma unroll 4
        for (int r = 0; r < 16; r++) {
            int row = w * 16 + r;
            float2 v = *(float2*)&stg[row * 68 + colp];
            size_t gr = (size_t)(r0 + row);
            const unsigned char* mp = mask + ((size_t)b * SS + gr) * SS + c0 + colg;
            v.x = mp[0] ? -1e9f : v.x * 0.125f;
            v.y = mp[1] ? -1e9f : v.y * 0.125f;
            *(float2*)(attn + ((size_t)bh * SS + gr) * SS + c0 + colg) = v;
            float mx = fmaxf(v.x, v.y);
            #pragma unroll
            for (int o = 16; o; o >>= 1) mx = fmaxf(mx, __shfl_xor_sync(0xffffffffu, mx, o));
            float s = __expf(v.x - mx) + __expf(v.y - mx);
            #pragma unroll
            for (int o = 16; o; o >>= 1) s += __shfl_xor_sync(0xffffffffu, s, o);
            if (lane == 0) {
                size_t idx = ((size_t)bh * SS + gr) * NCT + blockIdx.x;
                g_smax[idx] = mx;
                g_ssum[idx] = s;
            }
        }
    }
}

// ---------------------------------------------------------------------------
// Combine tile stats into per-row max and 1/sum. One warp per row.
// ---------------------------------------------------------------------------
__global__ __launch_bounds__(256) void softmax_stats(
    float* __restrict__ rowm, float* __restrict__ rinv)
{
    const int w = threadIdx.x >> 5, lane = threadIdx.x & 31;
    const size_t rg = (size_t)blockIdx.x * 8 + w;
    float m_l = g_smax[rg * NCT + lane];
    float s_l = g_ssum[rg * NCT + lane];
    float m = m_l;
    #pragma unroll
    for (int o = 16; o; o >>= 1) m = fmaxf(m, __shfl_xor_sync(0xffffffffu, m, o));
    float c = __expf(m_l - m) * s_l;
    #pragma unroll
    for (int o = 16; o; o >>= 1) c += __shfl_xor_sync(0xffffffffu, c, o);
    if (lane == 0) { rowm[rg] = m; rinv[rg] = 1.0f / c; }
}

// ---------------------------------------------------------------------------
// GEMM: C = A[M,512] @ W[512,512] + bias (+resid). Block 128x64, 256 thr,
// double-buffered cp.async. SPLIT=1: 3-product hi/lo; SPLIT=0: plain bf16.
// OUTLO=1: write bf16 hi+lo head-major; OUTLO=0: hi only (when !OUTPROJ).
// ---------------------------------------------------------------------------
template<int SPLIT>
struct GOff {
    static const unsigned AH = 0;
    static const unsigned AL = 20480;
    static const unsigned WH = SPLIT ? 40960u : 20480u;
    static const unsigned WL = 50176;
    static const unsigned ABUF = 10240;
    static const unsigned WBUF = 4608;
    static const unsigned SMEM = SPLIT ? 59392u : 29696u;
};

template<int SPLIT>
__device__ __forceinline__ void gload(
    unsigned sb, int buf,
    const __nv_bfloat16* __restrict__ Ah, const __nv_bfloat16* __restrict__ Al,
    const __nv_bfloat16* __restrict__ Wh, const __nv_bfloat16* __restrict__ Wl,
    int row0, int col0, int kk, int t)
{
    #pragma unroll
    for (int i = 0; i < 2; i++) {
        int ch = t + i * 256;
        int r = ch >> 2, c = (ch & 3) * 8;
        unsigned off = buf * GOff<SPLIT>::ABUF + r * 80 + c * 2;
        cp16(sb + GOff<SPLIT>::AH + off, Ah + (size_t)(row0 + r) * 512 + kk + c);
        if (SPLIT)
            cp16(sb + GOff<SPLIT>::AL + off, Al + (size_t)(row0 + r) * 512 + kk + c);
    }
    {
        int r = t >> 3, c = (t & 7) * 8;
        unsigned off = buf * GOff<SPLIT>::WBUF + r * 144 + c * 2;
        cp16(sb + GOff<SPLIT>::WH + off, Wh + (size_t)(kk + r) * 512 + col0 + c);
        if (SPLIT)
            cp16(sb + GOff<SPLIT>::WL + off, Wl + (size_t)(kk + r) * 512 + col0 + c);
    }
}

template<int OUTPROJ, int SPLIT, int OUTLO>
__global__ __launch_bounds__(256, 3) void mma_gemm512(
    const __nv_bfloat16* __restrict__ Ah, const __nv_bfloat16* __restrict__ Al,
    const __nv_bfloat16* __restrict__ Wh, const __nv_bfloat16* __restrict__ Wl,
    const float* __restrict__ bias, const float* __restrict__ resid,
    __nv_bfloat16* __restrict__ Oh, __nv_bfloat16* __restrict__ Ol,
    float* __restrict__ Of)
{
    extern __shared__ __align__(16) char smem_raw[];
    const unsigned sb = sptr(smem_raw);
    const int t = threadIdx.x, lane = t & 31, w = t >> 5;
    const int wm = w & 3, wn = w >> 2;
    const int row0 = blockIdx.y * 128, col0 = blockIdx.x * 64;

    float acc[2][4][4] = {};

    gload<SPLIT>(sb, 0, Ah, Al, Wh, Wl, row0, col0, 0, t);
    cp_commit();

    for (int it = 0; it < 16; it++) {
        if (it < 15)
            gload<SPLIT>(sb, (it + 1) & 1, Ah, Al, Wh, Wl, row0, col0, (it + 1) * 32, t);
        cp_commit();
        cp_wait1();
        __syncthreads();

        const unsigned abh = sb + GOff<SPLIT>::AH + (it & 1) * GOff<SPLIT>::ABUF;
        const unsigned abl = sb + GOff<SPLIT>::AL + (it & 1) * GOff<SPLIT>::ABUF;
        const unsigned wbh = sb + GOff<SPLIT>::WH + (it & 1) * GOff<SPLIT>::WBUF;
        const unsigned wbl = sb + GOff<SPLIT>::WL + (it & 1) * GOff<SPLIT>::WBUF;

        #pragma unroll
        for (int k2 = 0; k2 < 32; k2 += 16) {
            unsigned ah[2][4], al[2][4];
            #pragma unroll
            for (int mi = 0; mi < 2; mi++) {
                int r = wm * 32 + mi * 16 + (lane & 15);
                int c = k2 + ((lane >> 4) << 3);
                ldsm4(ah[mi], abh + r * 80 + c * 2);
                if (SPLIT) ldsm4(al[mi], abl + r * 80 + c * 2);
            }
            #pragma unroll
            for (int g = 0; g < 2; g++) {
                int kr = k2 + (lane & 7) + (((lane >> 3) & 1) << 3);
                int nc = wn * 32 + g * 16 + ((lane >> 4) << 3);
                unsigned bh_[4], bl_[4];
                ldsm4t(bh_, wbh + kr * 144 + nc * 2);
                if (SPLIT) ldsm4t(bl_, wbl + kr * 144 + nc * 2);
                #pragma unroll
                for (int mi = 0; mi < 2; mi++) {
                    mma_bf16(acc[mi][2*g],   ah[mi], &bh_[0]);
                    mma_bf16(acc[mi][2*g+1], ah[mi], &bh_[2]);
                    if (SPLIT) {
                        mma_bf16(acc[mi][2*g],   ah[mi], &bl_[0]);
                        mma_bf16(acc[mi][2*g+1], ah[mi], &bl_[2]);
                        mma_bf16(acc[mi][2*g],   al[mi], &bh_[0]);
                        mma_bf16(acc[mi][2*g+1], al[mi], &bh_[2]);
                    }
                }
            }
        }
        __syncthreads();
    }

    #pragma unroll
    for (int mi = 0; mi < 2; mi++) {
        #pragma unroll
        for (int nf = 0; nf < 4; nf++) {
            float* c = acc[mi][nf];
            int m = row0 + wm * 32 + mi * 16 + (lane >> 2);
            int n = col0 + wn * 32 + nf * 8 + ((lane & 3) << 1);
            float b0 = bias[n], b1 = bias[n + 1];
            if (OUTPROJ) {
                float2 r = *(const float2*)(resid + (size_t)m * 512 + n);
                *(float2*)(Of + (size_t)m * 512 + n) =
                    make_float2(c[0] + b0 + r.x, c[1] + b1 + r.y);
                r = *(const float2*)(resid + (size_t)(m + 8) * 512 + n);
                *(float2*)(Of + (size_t)(m + 8) * 512 + n) =
                    make_float2(c[2] + b0 + r.x, c[3] + b1 + r.y);
            } else {
                int h = n >> 6, d = n & 63;
                int b = m >> 11, s = m & 2047;
                size_t base = ((size_t)(b * NH + h) * SS + s) * DK + d;
                if (OUTLO) {
                    __nv_bfloat162 h2, l2;
                    split_pair(c[0] + b0, c[1] + b1, h2, l2);
                    *(__nv_bfloat162*)&Oh[base] = h2;
                    *(__nv_bfloat162*)&Ol[base] = l2;
                    split_pair(c[2] + b0, c[3] + b1, h2, l2);
                    *(__nv_bfloat162*)&Oh[base + 8 * (size_t)DK] = h2;
                    *(__nv_bfloat162*)&Ol[base + 8 * (size_t)DK] = l2;
                } else {
                    *(__nv_bfloat162*)&Oh[base] =
                        __float22bfloat162_rn(make_float2(c[0] + b0, c[1] + b1));
                    *(__nv_bfloat162*)&Oh[base + 8 * (size_t)DK] =
                        __float22bfloat162_rn(make_float2(c[2] + b0, c[3] + b1));
                }
            }
        }
    }
}

// ---------------------------------------------------------------------------
// Context + softmax normalize, pure bf16 P and V (precision budget).
// Reads raw scores, writes probs in-place, ctx = P @ V stored bf16.
// ---------------------------------------------------------------------------
__global__ __launch_bounds__(256, 2) void mma_context(
    float* __restrict__ attn, const float* __restrict__ rowm,
    const float* __restrict__ rinv, __nv_bfloat16* __restrict__ ctxh)
{
    __shared__ __align__(16) __nv_bfloat16 Ph[128][72];
    __shared__ __align__(16) __nv_bfloat16 Vh[64][72];
    const int t = threadIdx.x, lane = t & 31, w = t >> 5;
    const int wm = w & 3, wn = w >> 2;
    const int bh = blockIdx.y, r0 = blockIdx.x * 128;
    const size_t vbase = (size_t)bh * SS * DK;

    const int pr = t >> 1, pc = (t & 1) * 32;
    const float rm = __ldg(rowm + (size_t)bh * SS + r0 + pr);
    const float ri = __ldg(rinv + (size_t)bh * SS + r0 + pr);
    float* prow = attn + (size_t)bh * SS * SS + (size_t)(r0 + pr) * SS + pc;

    float acc[2][4][4] = {};

    for (int kk = 0; kk < SS; kk += 64) {
        {   // V chunk 64x64 bf16: 512 chunks of 16B, 2/thread
            #pragma unroll
            for (int i = 0; i < 2; i++) {
                int idx = t + i * 256;
                int vr = idx >> 3, vc = (idx & 7) * 8;
                cp16(sptr(&Vh[vr][vc]), g_vh + vbase + (size_t)(kk + vr) * 64 + vc);
            }
        }
        {   // P chunk: exp-normalize + write probs + pack bf16
            float* p = prow + kk;
            #pragma unroll
            for (int i = 0; i < 32; i += 4) {
                float4 v = *(float4*)(p + i);
                v.x = __expf(v.x - rm) * ri;
                v.y = __expf(v.y - rm) * ri;
                v.z = __expf(v.z - rm) * ri;
                v.w = __expf(v.w - rm) * ri;
                *(float4*)(p + i) = v;               // final attn probabilities
                *(__nv_bfloat162*)&Ph[pr][pc + i] =
                    __float22bfloat162_rn(make_float2(v.x, v.y));
                *(__nv_bfloat162*)&Ph[pr][pc + i + 2] =
                    __float22bfloat162_rn(make_float2(v.z, v.w));
            }
        }
        cp_commit();
        cp_wait0();
        __syncthreads();
        #pragma unroll
        for (int k2 = 0; k2 < 64; k2 += 16) {
            unsigned ah[2][4];
            #pragma unroll
            for (int mi = 0; mi < 2; mi++) {
                int r = wm * 32 + mi * 16 + (lane & 15);
                int c = k2 + ((lane >> 4) << 3);
                ldsm4(ah[mi], sptr(&Ph[r][c]));
            }
            #pragma unroll
            for (int g = 0; g < 2; g++) {
                int kr = k2 + (lane & 7) + (((lane >> 3) & 1) << 3);
                int nc = wn * 32 + g * 16 + ((lane >> 4) << 3);
                unsigned bh_[4];
                ldsm4t(bh_, sptr(&Vh[kr][nc]));
                #pragma unroll
                for (int mi = 0; mi < 2; mi++) {
                    mma_bf16(acc[mi][2*g],   ah[mi], &bh_[0]);
                    mma_bf16(acc[mi][2*g+1], ah[mi], &bh_[2]);
                }
            }
        }
        __syncthreads();
    }

    const int b = bh >> 3, h = bh & 7;
    #pragma unroll
    for (int mi = 0; mi < 2; mi++) {
        #pragma unroll
        for (int nf = 0; nf < 4; nf++) {
            float* c = acc[mi][nf];
            int m = r0 + wm * 32 + mi * 16 + (lane >> 2);
            int n = wn * 32 + nf * 8 + ((lane & 3) << 1);
            size_t idx = ((size_t)(b * SS + m)) * EMB + h * DK + n;
            *(__nv_bfloat162*)&ctxh[idx] =
                __float22bfloat162_rn(make_float2(c[0], c[1]));
            *(__nv_bfloat162*)&ctxh[idx + 8 * (size_t)EMB] =
                __float22bfloat162_rn(make_float2(c[2], c[3]));
        }
    }
}

// ---------------------------------------------------------------------------
// LayerNorm over 512.
// ---------------------------------------------------------------------------
__global__ __launch_bounds__(128) void ln_kernel(
    const float* __restrict__ gamma, const float* __restrict__ beta,
    float* __restrict__ out)
{
    const size_t row = blockIdx.x;
    const int t = threadIdx.x;
    const float* x = g_x + row * EMB;
    __shared__ float rs[4], rq[4];

    float4 v = ((const float4*)x)[t];
    float s  = v.x + v.y + v.z + v.w;
    float sq = v.x*v.x + v.y*v.y + v.z*v.z + v.w*v.w;
    #pragma unroll
    for (int o = 16; o; o >>= 1) {
        s  += __shfl_xor_sync(0xffffffffu, s,  o);
        sq += __shfl_xor_sync(0xffffffffu, sq, o);
    }
    if ((t & 31) == 0) { rs[t >> 5] = s; rq[t >> 5] = sq; }
    __syncthreads();
    s  = rs[0] + rs[1] + rs[2] + rs[3];
    sq = rq[0] + rq[1] + rq[2] + rq[3];

    float mu  = s * (1.0f / 512.0f);
    float var = sq * (1.0f / 512.0f) - mu * mu;
    float inv = rsqrtf(var + 1e-5f);

    float4 g = ((const float4*)gamma)[t];
    float4 bb = ((const float4*)beta)[t];
    float4 o;
    o.x = (v.x - mu) * inv * g.x + bb.x;
    o.y = (v.y - mu) * inv * g.y + bb.y;
    o.z = (v.z - mu) * inv * g.z + bb.z;
    o.w = (v.w - mu) * inv * g.w + bb.w;
    ((float4*)(out + row * EMB))[t] = o;
}

// ---------------------------------------------------------------------------
extern "C" void kernel_launch(void* const* d_in, const int* in_sizes, int n_in,
                              void* d_out, int out_size)
{
    const float* Q  = (const float*)d_in[0];
    const float* K  = (const float*)d_in[1];
    const float* V  = (const float*)d_in[2];
    const unsigned char* mask = (const unsigned char*)d_in[3];
    const float* Wq = (const float*)d_in[4];
    const float* bq = (const float*)d_in[5];
    const float* Wk = (const float*)d_in[6];
    const float* bk = (const float*)d_in[7];
    const float* Wv = (const float*)d_in[8];
    const float* bv = (const float*)d_in[9];
    const float* Wo = (const float*)d_in[10];
    const float* bo = (const float*)d_in[11];
    const float* gamma = (const float*)d_in[12];
    const float* beta  = (const float*)d_in[13];

    float* out  = (float*)d_out;
    float* attn = out + (size_t)BSROWS * EMB;

    __nv_bfloat16 *qh, *ql, *kh, *kl, *vh;
    __nv_bfloat16 *inqh, *inql, *inkh, *inkl, *invh;
    __nv_bfloat16 *wqh, *wql, *wkh, *wkl, *wvh, *woh;
    __nv_bfloat16 *ctxh;
    float *xp, *rowmp, *rinvp;
    cudaGetSymbolAddress((void**)&qh, g_qh);
    cudaGetSymbolAddress((void**)&ql, g_ql);
    cudaGetSymbolAddress((void**)&kh, g_kh);
    cudaGetSymbolAddress((void**)&kl, g_kl);
    cudaGetSymbolAddress((void**)&vh, g_vh);
    cudaGetSymbolAddress((void**)&inqh, g_inqh);
    cudaGetSymbolAddress((void**)&inql, g_inql);
    cudaGetSymbolAddress((void**)&inkh, g_inkh);
    cudaGetSymbolAddress((void**)&inkl, g_inkl);
    cudaGetSymbolAddress((void**)&invh, g_invh);
    cudaGetSymbolAddress((void**)&wqh, g_wqh);
    cudaGetSymbolAddress((void**)&wql, g_wql);
    cudaGetSymbolAddress((void**)&wkh, g_wkh);
    cudaGetSymbolAddress((void**)&wkl, g_wkl);
    cudaGetSymbolAddress((void**)&wvh, g_wvh);
    cudaGetSymbolAddress((void**)&woh, g_woh);
    cudaGetSymbolAddress((void**)&ctxh, g_ctxh);
    cudaGetSymbolAddress((void**)&xp,   g_x);
    cudaGetSymbolAddress((void**)&rowmp, g_rowm);
    cudaGetSymbolAddress((void**)&rinvp, g_rinv);

    cudaFuncSetAttribute(mma_scores, cudaFuncAttributeMaxDynamicSharedMemorySize,
                         SC_SMEM);
    cudaFuncSetAttribute(mma_gemm512<0,1,1>, cudaFuncAttributeMaxDynamicSharedMemorySize,
                         GOff<1>::SMEM);
    cudaFuncSetAttribute(mma_gemm512<0,0,0>, cudaFuncAttributeMaxDynamicSharedMemorySize,
                         GOff<0>::SMEM);
    cudaFuncSetAttribute(mma_gemm512<1,0,0>, cudaFuncAttributeMaxDynamicSharedMemorySize,
                         GOff<0>::SMEM);

    // convert inputs + weights
    const int n4_in = BSROWS * EMB / 4;       // 1,048,576
    const int n4_w  = EMB * EMB / 4;          // 65,536
    split_f32<<<n4_in / 256, 256>>>(Q, inqh, inql, n4_in);
    split_f32<<<n4_in / 256, 256>>>(K, inkh, inkl, n4_in);
    tobf16_f32<<<n4_in / 256, 256>>>(V, invh, n4_in);
    split_f32<<<n4_w / 256, 256>>>(Wq, wqh, wql, n4_w);
    split_f32<<<n4_w / 256, 256>>>(Wk, wkh, wkl, n4_w);
    tobf16_f32<<<n4_w / 256, 256>>>(Wv, wvh, n4_w);
    tobf16_f32<<<n4_w / 256, 256>>>(Wo, woh, n4_w);

    dim3 gemm_grid(EMB / 64, BSROWS / 128);        // 8 x 64
    mma_gemm512<0,1,1><<<gemm_grid, 256, GOff<1>::SMEM>>>(
        inqh, inql, wqh, wql, bq, nullptr, qh, ql, nullptr);
    mma_gemm512<0,1,1><<<gemm_grid, 256, GOff<1>::SMEM>>>(
        inkh, inkl, wkh, wkl, bk, nullptr, kh, kl, nullptr);
    mma_gemm512<0,0,0><<<gemm_grid, 256, GOff<0>::SMEM>>>(
        invh, nullptr, wvh, nullptr, bv, nullptr, vh, nullptr, nullptr);

    dim3 sc_grid(SS / 64, SS / 128, BH);           // 32 x 16 x 32
    mma_scores<<<sc_grid, 256, SC_SMEM>>>(mask, attn);

    softmax_stats<<<(BH * SS) / 8, 256>>>(rowmp, rinvp);

    dim3 ctx_grid(SS / 128, BH);                   // 16 x 32
    mma_context<<<ctx_grid, 256>>>(attn, rowmp, rinvp, ctxh);

    mma_gemm512<1,0,0><<<gemm_grid, 256, GOff<0>::SMEM>>>(
        ctxh, nullptr, woh, nullptr, bo, Q, nullptr, nullptr, xp);

    ln_kernel<<<BSROWS, 128>>>(gamma, beta, out);
}